// round 7
// baseline (speedup 1.0000x reference)
#include <cuda_runtime.h>
#include <math.h>

#define N_MAX 100000
#define E_MAX 3200000
typedef unsigned long long ull;

// ---- scratch (static __device__ arrays; allocation-free) ----
__device__ __align__(16) float g_A[N_MAX * 32];
__device__ __align__(16) float g_B[N_MAX * 32];
__device__ __align__(16) float g_sumenc[N_MAX * 4];
__device__ __align__(16) float g_cnt[N_MAX];
__device__ __align__(16) float g_sumout[N_MAX * 4];
__device__ __align__(16) float g_stats[8];
__device__ __align__(16) int   g_hist[N_MAX];
__device__ __align__(16) int   g_pos[N_MAX];
__device__ __align__(16) int2  g_edges[E_MAX];   // sorted by tgt: (src, tgt)

// ---- f32x2 / LDS / red helpers ----
__device__ __forceinline__ ull pack2(float x, float y) {
    ull r; asm("mov.b64 %0, {%1,%2};" : "=l"(r) : "f"(x), "f"(y)); return r;
}
__device__ __forceinline__ void unpack2(ull v, float& x, float& y) {
    asm("mov.b64 {%0,%1}, %2;" : "=f"(x), "=f"(y) : "l"(v));
}
__device__ __forceinline__ void fma2(ull& d, ull a, ull b) {
    asm("fma.rn.f32x2 %0, %1, %2, %3;" : "=l"(d) : "l"(a), "l"(b), "l"(d));
}
__device__ __forceinline__ ull addp(ull a, ull b) {
    ull r; asm("add.rn.f32x2 %0, %1, %2;" : "=l"(r) : "l"(a), "l"(b)); return r;
}
__device__ __forceinline__ void lds_pair(unsigned addr, ull& a, ull& b) {
    asm volatile("ld.shared.v2.u64 {%0,%1}, [%2];" : "=l"(a), "=l"(b) : "r"(addr));
}
__device__ __forceinline__ void red4(float* p, float a, float b, float c, float d) {
    asm volatile("red.global.add.v4.f32 [%0], {%1,%2,%3,%4};"
                 :: "l"(p), "f"(a), "f"(b), "f"(c), "f"(d) : "memory");
}
__device__ __forceinline__ ull shflx(ull v, int m) {
    return __shfl_xor_sync(0xffffffffu, v, m);
}

// quad reduce-scatter: acc[16] (32 outputs, k-partial) -> t4[4]
__device__ __forceinline__ void quad_rs(const ull acc[16], int qlane, ull t4[4]) {
    ull t8[8];
    bool hi2 = (qlane & 2) != 0;
    #pragma unroll
    for (int i = 0; i < 8; i++) {
        ull sel  = hi2 ? acc[i]     : acc[i + 8];
        ull keep = hi2 ? acc[i + 8] : acc[i];
        t8[i] = addp(keep, shflx(sel, 2));
    }
    bool hi1 = (qlane & 1) != 0;
    #pragma unroll
    for (int i = 0; i < 4; i++) {
        ull sel  = hi1 ? t8[i]     : t8[i + 4];
        ull keep = hi1 ? t8[i + 4] : t8[i];
        t4[i] = addp(keep, shflx(sel, 1));
    }
}

// ---- K0: zero accumulators ----
__global__ void k_zero(int n) {
    int i = blockIdx.x * blockDim.x + threadIdx.x;
    int stride = gridDim.x * blockDim.x;
    float4 z = make_float4(0.f, 0.f, 0.f, 0.f);
    float4* a = (float4*)g_sumenc; int na = n;
    for (int t = i; t < na; t += stride) a[t] = z;
    float4* b = (float4*)g_sumout; int nb = n;
    for (int t = i; t < nb; t += stride) b[t] = z;
    int4* h = (int4*)g_hist; int nh = n >> 2;
    int4 zi = make_int4(0, 0, 0, 0);
    for (int t = i; t < nh; t += stride) h[t] = zi;
    if (i < 8) g_stats[i] = 0.f;
    if (i == 0) { g_hist[n & ~3] = 0; }  // safety (n may not be /4; handled below anyway)
}

// ---- K0b: zero hist tail (n not multiple of 4) ----
__global__ void k_zero_tail(int n) {
    int i = (n & ~3) + threadIdx.x;
    if (threadIdx.x < 4 && i < n) g_hist[i] = 0;
}

// ---- K1: batchnorm statistics ----
__global__ void k_stats(const float4* __restrict__ x, int n) {
    float sx = 0, sy = 0, sz = 0, sw = 0, qx = 0, qy = 0, qz = 0, qw = 0;
    for (int i = blockIdx.x * blockDim.x + threadIdx.x; i < n; i += gridDim.x * blockDim.x) {
        float4 v = x[i];
        sx += v.x; sy += v.y; sz += v.z; sw += v.w;
        qx += v.x * v.x; qy += v.y * v.y; qz += v.z * v.z; qw += v.w * v.w;
    }
    #pragma unroll
    for (int off = 16; off; off >>= 1) {
        sx += __shfl_down_sync(0xffffffffu, sx, off);
        sy += __shfl_down_sync(0xffffffffu, sy, off);
        sz += __shfl_down_sync(0xffffffffu, sz, off);
        sw += __shfl_down_sync(0xffffffffu, sw, off);
        qx += __shfl_down_sync(0xffffffffu, qx, off);
        qy += __shfl_down_sync(0xffffffffu, qy, off);
        qz += __shfl_down_sync(0xffffffffu, qz, off);
        qw += __shfl_down_sync(0xffffffffu, qw, off);
    }
    if ((threadIdx.x & 31) == 0) {
        atomicAdd(&g_stats[0], sx); atomicAdd(&g_stats[1], sy);
        atomicAdd(&g_stats[2], sz); atomicAdd(&g_stats[3], sw);
        atomicAdd(&g_stats[4], qx); atomicAdd(&g_stats[5], qy);
        atomicAdd(&g_stats[6], qz); atomicAdd(&g_stats[7], qw);
    }
}

// ---- sort pass 1: histogram of tgt ----
__global__ void k_hist(const int* __restrict__ ei, int E) {
    int e = blockIdx.x * blockDim.x + threadIdx.x;
    if (e < E) atomicAdd(&g_hist[ei[E + e]], 1);
}

// ---- sort pass 2: exclusive scan (single block, 1024 threads) + cnt ----
__global__ void k_scan(int n) {
    __shared__ int wsum[32];
    __shared__ int s_carry;
    int t = threadIdx.x;
    if (t == 0) s_carry = 0;
    __syncthreads();
    for (int base = 0; base < n; base += 1024) {
        int i = base + t;
        int h = (i < n) ? g_hist[i] : 0;
        int v = h;
        #pragma unroll
        for (int d = 1; d < 32; d <<= 1) {
            int u = __shfl_up_sync(0xffffffffu, v, d);
            if ((t & 31) >= d) v += u;
        }
        if ((t & 31) == 31) wsum[t >> 5] = v;
        __syncthreads();
        if (t < 32) {
            int w = wsum[t];
            #pragma unroll
            for (int d = 1; d < 32; d <<= 1) {
                int u = __shfl_up_sync(0xffffffffu, w, d);
                if (t >= d) w += u;
            }
            wsum[t] = w;
        }
        __syncthreads();
        int excl = v - h + s_carry + ((t >= 32) ? wsum[(t >> 5) - 1] : 0);
        if (i < n) {
            g_pos[i] = excl;
            g_cnt[i] = (float)h;
        }
        __syncthreads();
        if (t == 1023) s_carry = excl + h;
        __syncthreads();
    }
}

// ---- sort pass 3: permute edges into tgt-sorted order ----
__global__ void k_perm(const int* __restrict__ ei, int E) {
    int e = blockIdx.x * blockDim.x + threadIdx.x;
    if (e < E) {
        int s = ei[e], tg = ei[E + e];
        int p = atomicAdd(&g_pos[tg], 1);
        g_edges[p] = make_int2(s, tg);
    }
}

// ---- K2: BN + encoder layer-1 split ----
__global__ void k_pre(const float4* __restrict__ x,
                      const float* __restrict__ gamma, const float* __restrict__ beta,
                      const float* __restrict__ eW1, const float* __restrict__ eb1,
                      int n, float invN) {
    __shared__ float sWd[128], sWb[128], sb1[32], sScale[4], sShift[4];
    int t = threadIdx.x;
    if (t < 128) {
        int c = t >> 5, o = t & 31;
        float wa = eW1[c * 32 + o], wb = eW1[(4 + c) * 32 + o];
        sWd[t] = wa - wb; sWb[t] = wb;
    }
    if (t < 32) sb1[t] = eb1[t];
    if (t < 4) {
        float m = g_stats[t] * invN;
        float v = g_stats[4 + t] * invN - m * m;
        float s = rsqrtf(v + 1e-5f) * gamma[t];
        sScale[t] = s; sShift[t] = beta[t] - m * s;
    }
    __syncthreads();
    for (int i = blockIdx.x * blockDim.x + t; i < n; i += gridDim.x * blockDim.x) {
        float4 xv = x[i];
        float xn[4];
        xn[0] = xv.x * sScale[0] + sShift[0];
        xn[1] = xv.y * sScale[1] + sShift[1];
        xn[2] = xv.z * sScale[2] + sShift[2];
        xn[3] = xv.w * sScale[3] + sShift[3];
        float a[32], b[32];
        #pragma unroll
        for (int o = 0; o < 32; o++) {
            float av = sb1[o], bv = 0.f;
            #pragma unroll
            for (int c = 0; c < 4; c++) {
                av += xn[c] * sWd[c * 32 + o];
                bv += xn[c] * sWb[c * 32 + o];
            }
            a[o] = av; b[o] = bv;
        }
        float4* Ao = (float4*)(g_A + (size_t)i * 32);
        float4* Bo = (float4*)(g_B + (size_t)i * 32);
        #pragma unroll
        for (int q = 0; q < 8; q++) {
            Ao[q] = make_float4(a[4*q], a[4*q+1], a[4*q+2], a[4*q+3]);
            Bo[q] = make_float4(b[4*q], b[4*q+1], b[4*q+2], b[4*q+3]);
        }
    }
}

// ===================== encoder edge pass (sorted edges, quad-coop, projected) =====================
__global__ void __launch_bounds__(128, 5) k_enc(const float* __restrict__ eW2,
                                                const float* __restrict__ eb2,
                                                const float* __restrict__ mW,
                                                const float* __restrict__ vW, int E) {
    __shared__ __align__(16) float sW[1024];
    __shared__ __align__(16) float sP[128];
    __shared__ __align__(16) float sb[32];
    for (int t = threadIdx.x; t < 1024; t += 128) {
        int k = t >> 5, c = (t >> 2) & 7, w = t & 3;
        sW[k * 32 + (((c + (k >> 2)) & 7) << 2) + w] = eW2[t];
    }
    if (threadIdx.x < 128) {
        int o = threadIdx.x >> 2, w = threadIdx.x & 3;
        float val = (w < 2) ? mW[o * 2 + w] : vW[o * 2 + (w - 2)];
        sP[(((o >> 3) + ((o & 7) << 2)) << 2) + w] = val;
    }
    if (threadIdx.x < 32) sb[threadIdx.x] = eb2[threadIdx.x];
    __syncthreads();
    unsigned swa = (unsigned)__cvta_generic_to_shared(sW);
    unsigned spa = (unsigned)__cvta_generic_to_shared(sP);
    unsigned sba = (unsigned)__cvta_generic_to_shared(sb);

    int lane = threadIdx.x & 31, warp = threadIdx.x >> 5;
    int qlane = lane & 3, qid = lane >> 2;
    int e0 = (blockIdx.x * 4 + warp) * 16 + qid * 2;
    if (e0 >= E) return;
    int4 pr = *(const int4*)(g_edges + e0);   // (src0, tgt0, src1, tgt1)
    int src0 = pr.x, tgt0 = pr.y, src1 = pr.z, tgt1 = pr.w;

    const float4* Ar0 = (const float4*)(g_A + (size_t)tgt0 * 32);
    const float4* Br0 = (const float4*)(g_B + (size_t)src0 * 32);
    const float4* Ar1 = (const float4*)(g_A + (size_t)tgt1 * 32);
    const float4* Br1 = (const float4*)(g_B + (size_t)src1 * 32);
    float4 al0 = __ldg(Ar0 + qlane), ah0 = __ldg(Ar0 + 4 + qlane);
    float4 bl0 = __ldg(Br0 + qlane), bh0 = __ldg(Br0 + 4 + qlane);
    float4 al1 = __ldg(Ar1 + qlane), ah1 = __ldg(Ar1 + 4 + qlane);
    float4 bl1 = __ldg(Br1 + qlane), bh1 = __ldg(Br1 + 4 + qlane);

    float u0[8], u1[8];
    u0[0] = fmaxf(al0.x + bl0.x, 0.f); u0[1] = fmaxf(al0.y + bl0.y, 0.f);
    u0[2] = fmaxf(al0.z + bl0.z, 0.f); u0[3] = fmaxf(al0.w + bl0.w, 0.f);
    u0[4] = fmaxf(ah0.x + bh0.x, 0.f); u0[5] = fmaxf(ah0.y + bh0.y, 0.f);
    u0[6] = fmaxf(ah0.z + bh0.z, 0.f); u0[7] = fmaxf(ah0.w + bh0.w, 0.f);
    u1[0] = fmaxf(al1.x + bl1.x, 0.f); u1[1] = fmaxf(al1.y + bl1.y, 0.f);
    u1[2] = fmaxf(al1.z + bl1.z, 0.f); u1[3] = fmaxf(al1.w + bl1.w, 0.f);
    u1[4] = fmaxf(ah1.x + bh1.x, 0.f); u1[5] = fmaxf(ah1.y + bh1.y, 0.f);
    u1[6] = fmaxf(ah1.z + bh1.z, 0.f); u1[7] = fmaxf(ah1.w + bh1.w, 0.f);

    ull acc0[16], acc1[16];
    #pragma unroll
    for (int i = 0; i < 16; i++) { acc0[i] = 0ull; acc1[i] = 0ull; }

    #pragma unroll
    for (int kk = 0; kk < 8; kk++) {
        int k = qlane * 4 + (kk & 3) + ((kk & 4) << 2);
        unsigned rot = (unsigned)(qlane + (kk & 4));
        unsigned rowa = swa + (unsigned)k * 128u;
        ull up0 = pack2(u0[kk], u0[kk]);
        ull up1 = pack2(u1[kk], u1[kk]);
        #pragma unroll
        for (int q = 0; q < 8; q++) {
            unsigned phys = (unsigned)(q + rot) & 7u;
            ull w0, w1;
            lds_pair(rowa + phys * 16u, w0, w1);
            fma2(acc0[2*q],   up0, w0);
            fma2(acc0[2*q+1], up0, w1);
            fma2(acc1[2*q],   up1, w0);
            fma2(acc1[2*q+1], up1, w1);
        }
    }

    ull t4a[4], t4b[4];
    quad_rs(acc0, qlane, t4a);
    quad_rs(acc1, qlane, t4b);

    ull bb0, bb1, bb2, bb3;
    lds_pair(sba + (unsigned)qlane * 32u, bb0, bb1);
    lds_pair(sba + (unsigned)qlane * 32u + 16u, bb2, bb3);
    t4a[0] = addp(t4a[0], bb0); t4a[1] = addp(t4a[1], bb1);
    t4a[2] = addp(t4a[2], bb2); t4a[3] = addp(t4a[3], bb3);
    t4b[0] = addp(t4b[0], bb0); t4b[1] = addp(t4b[1], bb1);
    t4b[2] = addp(t4b[2], bb2); t4b[3] = addp(t4b[3], bb3);

    float ma[8], mb_[8];
    unpack2(t4a[0], ma[0], ma[1]); unpack2(t4a[1], ma[2], ma[3]);
    unpack2(t4a[2], ma[4], ma[5]); unpack2(t4a[3], ma[6], ma[7]);
    unpack2(t4b[0], mb_[0], mb_[1]); unpack2(t4b[1], mb_[2], mb_[3]);
    unpack2(t4b[2], mb_[4], mb_[5]); unpack2(t4b[3], mb_[6], mb_[7]);
    #pragma unroll
    for (int i = 0; i < 8; i++) { ma[i] = fmaxf(ma[i], 0.f); mb_[i] = fmaxf(mb_[i], 0.f); }

    ull pa01 = 0, pa23 = 0, pb01 = 0, pb23 = 0;
    #pragma unroll
    for (int i = 0; i < 8; i++) {
        ull w0, w1;
        lds_pair(spa + (unsigned)((qlane + 4 * i) * 16), w0, w1);
        ull va = pack2(ma[i], ma[i]);
        ull vb2 = pack2(mb_[i], mb_[i]);
        fma2(pa01, va, w0); fma2(pa23, va, w1);
        fma2(pb01, vb2, w0); fma2(pb23, vb2, w1);
    }
    pa01 = addp(pa01, shflx(pa01, 1)); pa01 = addp(pa01, shflx(pa01, 2));
    pa23 = addp(pa23, shflx(pa23, 1)); pa23 = addp(pa23, shflx(pa23, 2));
    pb01 = addp(pb01, shflx(pb01, 1)); pb01 = addp(pb01, shflx(pb01, 2));
    pb23 = addp(pb23, shflx(pb23, 1)); pb23 = addp(pb23, shflx(pb23, 2));

    if (qlane == 0) {
        float f0, f1, f2, f3, h0, h1, h2, h3;
        unpack2(pa01, f0, f1); unpack2(pa23, f2, f3);
        unpack2(pb01, h0, h1); unpack2(pb23, h2, h3);
        if (tgt0 == tgt1) {
            red4(g_sumenc + (size_t)tgt0 * 4, f0 + h0, f1 + h1, f2 + h2, f3 + h3);
        } else {
            red4(g_sumenc + (size_t)tgt0 * 4, f0, f1, f2, f3);
            red4(g_sumenc + (size_t)tgt1 * 4, h0, h1, h2, h3);
        }
    }
}

// ---- K4: per-node mid ----
__global__ void k_mid(const float* __restrict__ mb, const float* __restrict__ vb,
                      const float* __restrict__ dW1, const float* __restrict__ db1,
                      const float* __restrict__ eps2,
                      float* __restrict__ out_mu, float* __restrict__ out_lv, int n) {
    __shared__ float sWd[64], sWb[64], sdb1[32], smb[2], svb[2];
    int t = threadIdx.x;
    if (t < 32) {
        sdb1[t] = db1[t];
        sWd[t]      = dW1[t]      - dW1[64 + t];
        sWd[32 + t] = dW1[32 + t] - dW1[96 + t];
        sWb[t]      = dW1[64 + t];
        sWb[32 + t] = dW1[96 + t];
    }
    if (t < 2) { smb[t] = mb[t]; svb[t] = vb[t]; }
    __syncthreads();
    for (int i = blockIdx.x * blockDim.x + t; i < n; i += gridDim.x * blockDim.x) {
        float4 s = ((const float4*)g_sumenc)[i];
        float inv = 1.0f / fmaxf(g_cnt[i], 1.0f);
        float mu0 = s.x * inv + smb[0];
        float mu1 = s.y * inv + smb[1];
        float lv0 = s.z * inv + svb[0];
        float lv1 = s.w * inv + svb[1];
        float2 ep = ((const float2*)eps2)[i];
        float z0 = mu0 + ep.x * expf(0.5f * lv0);
        float z1 = mu1 + ep.y * expf(0.5f * lv1);
        ((float2*)out_mu)[i] = make_float2(mu0, mu1);
        ((float2*)out_lv)[i] = make_float2(lv0, lv1);
        float a[32], b[32];
        #pragma unroll
        for (int o = 0; o < 32; o++) {
            a[o] = sdb1[o] + z0 * sWd[o] + z1 * sWd[32 + o];
            b[o] = z0 * sWb[o] + z1 * sWb[32 + o];
        }
        float4* Ao = (float4*)(g_A + (size_t)i * 32);
        float4* Bo = (float4*)(g_B + (size_t)i * 32);
        #pragma unroll
        for (int q = 0; q < 8; q++) {
            Ao[q] = make_float4(a[4*q], a[4*q+1], a[4*q+2], a[4*q+3]);
            Bo[q] = make_float4(b[4*q], b[4*q+1], b[4*q+2], b[4*q+3]);
        }
    }
}

// ===================== decoder edge pass (sorted edges, quad-coop) =====================
__global__ void __launch_bounds__(128, 5) k_dec(const float* __restrict__ dW2,
                                                const float* __restrict__ db2,
                                                const float* __restrict__ dW3,
                                                const float* __restrict__ db3, int E) {
    __shared__ __align__(16) float sW[1024];
    __shared__ __align__(16) float sW3[128];
    __shared__ __align__(16) float sb[32];
    __shared__ __align__(16) float sb3[4];
    for (int t = threadIdx.x; t < 1024; t += 128) {
        int k = t >> 5, c = (t >> 2) & 7, w = t & 3;
        sW[k * 32 + (((c + (k >> 2)) & 7) << 2) + w] = dW2[t];
    }
    if (threadIdx.x < 128) {
        int o = threadIdx.x >> 2, w = threadIdx.x & 3;
        sW3[((4 * (o & 7) + (o >> 3)) << 2) + w] = dW3[threadIdx.x];
    }
    if (threadIdx.x < 32) sb[threadIdx.x] = db2[threadIdx.x];
    if (threadIdx.x < 4)  sb3[threadIdx.x] = db3[threadIdx.x];
    __syncthreads();
    unsigned swa  = (unsigned)__cvta_generic_to_shared(sW);
    unsigned sw3a = (unsigned)__cvta_generic_to_shared(sW3);
    unsigned sba  = (unsigned)__cvta_generic_to_shared(sb);
    unsigned sb3a = (unsigned)__cvta_generic_to_shared(sb3);

    int lane = threadIdx.x & 31, warp = threadIdx.x >> 5;
    int qlane = lane & 3, qid = lane >> 2;
    int e0 = (blockIdx.x * 4 + warp) * 16 + qid * 2;
    if (e0 >= E) return;
    int4 pr = *(const int4*)(g_edges + e0);
    int src0 = pr.x, tgt0 = pr.y, src1 = pr.z, tgt1 = pr.w;

    const float4* Ar0 = (const float4*)(g_A + (size_t)tgt0 * 32);
    const float4* Br0 = (const float4*)(g_B + (size_t)src0 * 32);
    const float4* Ar1 = (const float4*)(g_A + (size_t)tgt1 * 32);
    const float4* Br1 = (const float4*)(g_B + (size_t)src1 * 32);
    float4 al0 = __ldg(Ar0 + qlane), ah0 = __ldg(Ar0 + 4 + qlane);
    float4 bl0 = __ldg(Br0 + qlane), bh0 = __ldg(Br0 + 4 + qlane);
    float4 al1 = __ldg(Ar1 + qlane), ah1 = __ldg(Ar1 + 4 + qlane);
    float4 bl1 = __ldg(Br1 + qlane), bh1 = __ldg(Br1 + 4 + qlane);

    float u0[8], u1[8];
    u0[0] = fmaxf(al0.x + bl0.x, 0.f); u0[1] = fmaxf(al0.y + bl0.y, 0.f);
    u0[2] = fmaxf(al0.z + bl0.z, 0.f); u0[3] = fmaxf(al0.w + bl0.w, 0.f);
    u0[4] = fmaxf(ah0.x + bh0.x, 0.f); u0[5] = fmaxf(ah0.y + bh0.y, 0.f);
    u0[6] = fmaxf(ah0.z + bh0.z, 0.f); u0[7] = fmaxf(ah0.w + bh0.w, 0.f);
    u1[0] = fmaxf(al1.x + bl1.x, 0.f); u1[1] = fmaxf(al1.y + bl1.y, 0.f);
    u1[2] = fmaxf(al1.z + bl1.z, 0.f); u1[3] = fmaxf(al1.w + bl1.w, 0.f);
    u1[4] = fmaxf(ah1.x + bh1.x, 0.f); u1[5] = fmaxf(ah1.y + bh1.y, 0.f);
    u1[6] = fmaxf(ah1.z + bh1.z, 0.f); u1[7] = fmaxf(ah1.w + bh1.w, 0.f);

    ull acc0[16], acc1[16];
    #pragma unroll
    for (int i = 0; i < 16; i++) { acc0[i] = 0ull; acc1[i] = 0ull; }

    #pragma unroll
    for (int kk = 0; kk < 8; kk++) {
        int k = qlane * 4 + (kk & 3) + ((kk & 4) << 2);
        unsigned rot = (unsigned)(qlane + (kk & 4));
        unsigned rowa = swa + (unsigned)k * 128u;
        ull up0 = pack2(u0[kk], u0[kk]);
        ull up1 = pack2(u1[kk], u1[kk]);
        #pragma unroll
        for (int q = 0; q < 8; q++) {
            unsigned phys = (unsigned)(q + rot) & 7u;
            ull w0, w1;
            lds_pair(rowa + phys * 16u, w0, w1);
            fma2(acc0[2*q],   up0, w0);
            fma2(acc0[2*q+1], up0, w1);
            fma2(acc1[2*q],   up1, w0);
            fma2(acc1[2*q+1], up1, w1);
        }
    }

    ull t4a[4], t4b[4];
    quad_rs(acc0, qlane, t4a);
    quad_rs(acc1, qlane, t4b);

    ull bb0, bb1, bb2, bb3;
    lds_pair(sba + (unsigned)qlane * 32u, bb0, bb1);
    lds_pair(sba + (unsigned)qlane * 32u + 16u, bb2, bb3);
    t4a[0] = addp(t4a[0], bb0); t4a[1] = addp(t4a[1], bb1);
    t4a[2] = addp(t4a[2], bb2); t4a[3] = addp(t4a[3], bb3);
    t4b[0] = addp(t4b[0], bb0); t4b[1] = addp(t4b[1], bb1);
    t4b[2] = addp(t4b[2], bb2); t4b[3] = addp(t4b[3], bb3);

    float va[8], vb_[8];
    unpack2(t4a[0], va[0], va[1]); unpack2(t4a[1], va[2], va[3]);
    unpack2(t4a[2], va[4], va[5]); unpack2(t4a[3], va[6], va[7]);
    unpack2(t4b[0], vb_[0], vb_[1]); unpack2(t4b[1], vb_[2], vb_[3]);
    unpack2(t4b[2], vb_[4], vb_[5]); unpack2(t4b[3], vb_[6], vb_[7]);
    #pragma unroll
    for (int i = 0; i < 8; i++) { va[i] = fmaxf(va[i], 0.f); vb_[i] = fmaxf(vb_[i], 0.f); }

    ull oc0a = 0, oc1a = 0, oc0b = 0, oc1b = 0;
    #pragma unroll
    for (int i = 0; i < 8; i++) {
        ull w0, w1;
        lds_pair(sw3a + (unsigned)((4 * i + qlane) * 16), w0, w1);
        ull vp0 = pack2(va[i], va[i]);
        ull vp1 = pack2(vb_[i], vb_[i]);
        fma2(oc0a, vp0, w0); fma2(oc1a, vp0, w1);
        fma2(oc0b, vp1, w0); fma2(oc1b, vp1, w1);
    }
    oc0a = addp(oc0a, shflx(oc0a, 1)); oc0a = addp(oc0a, shflx(oc0a, 2));
    oc1a = addp(oc1a, shflx(oc1a, 1)); oc1a = addp(oc1a, shflx(oc1a, 2));
    oc0b = addp(oc0b, shflx(oc0b, 1)); oc0b = addp(oc0b, shflx(oc0b, 2));
    oc1b = addp(oc1b, shflx(oc1b, 1)); oc1b = addp(oc1b, shflx(oc1b, 2));

    if (qlane == 0) {
        ull b0, b1;
        lds_pair(sb3a, b0, b1);
        ull r0 = addp(oc0a, b0), r1 = addp(oc1a, b1);
        ull s0 = addp(oc0b, b0), s1 = addp(oc1b, b1);
        float f0, f1, f2, f3, h0, h1, h2, h3;
        unpack2(r0, f0, f1); unpack2(r1, f2, f3);
        unpack2(s0, h0, h1); unpack2(s1, h2, h3);
        if (tgt0 == tgt1) {
            red4(g_sumout + (size_t)tgt0 * 4, f0 + h0, f1 + h1, f2 + h2, f3 + h3);
        } else {
            red4(g_sumout + (size_t)tgt0 * 4, f0, f1, f2, f3);
            red4(g_sumout + (size_t)tgt1 * 4, h0, h1, h2, h3);
        }
    }
}

// ---- K6: per-node output mean ----
__global__ void k_out(float* __restrict__ out, int n) {
    for (int i = blockIdx.x * blockDim.x + threadIdx.x; i < n; i += gridDim.x * blockDim.x) {
        float inv = 1.0f / fmaxf(g_cnt[i], 1.0f);
        float4 s = ((const float4*)g_sumout)[i];
        ((float4*)out)[i] = make_float4(s.x * inv, s.y * inv, s.z * inv, s.w * inv);
    }
}

extern "C" void kernel_launch(void* const* d_in, const int* in_sizes, int n_in,
                              void* d_out, int out_size) {
    const float* x     = (const float*)d_in[0];
    const int*   ei    = (const int*)d_in[1];
    const float* eps   = (const float*)d_in[2];
    const float* gamma = (const float*)d_in[3];
    const float* beta  = (const float*)d_in[4];
    const float* eW1   = (const float*)d_in[5];
    const float* eb1   = (const float*)d_in[6];
    const float* eW2   = (const float*)d_in[7];
    const float* eb2   = (const float*)d_in[8];
    const float* mW    = (const float*)d_in[9];
    const float* mb    = (const float*)d_in[10];
    const float* vW    = (const float*)d_in[11];
    const float* vb    = (const float*)d_in[12];
    const float* dW1   = (const float*)d_in[13];
    const float* db1   = (const float*)d_in[14];
    const float* dW2   = (const float*)d_in[15];
    const float* db2   = (const float*)d_in[16];
    const float* dW3   = (const float*)d_in[17];
    const float* db3   = (const float*)d_in[18];

    int n = in_sizes[0] / 4;
    int E = in_sizes[1] / 2;

    float* out    = (float*)d_out;
    float* out_mu = out + (size_t)n * 4;
    float* out_lv = out + (size_t)n * 6;

    int nb  = (n + 255) / 256;
    int ebE = (E + 255) / 256;
    int eb  = (E + 63) / 64;

    k_zero<<<256, 256>>>(n);
    k_zero_tail<<<1, 32>>>(n);
    k_stats<<<256, 256>>>((const float4*)x, n);
    k_hist<<<ebE, 256>>>(ei, E);
    k_scan<<<1, 1024>>>(n);
    k_perm<<<ebE, 256>>>(ei, E);
    k_pre<<<nb, 256>>>((const float4*)x, gamma, beta, eW1, eb1, n, 1.0f / (float)n);
    k_enc<<<eb, 128>>>(eW2, eb2, mW, vW, E);
    k_mid<<<nb, 256>>>(mb, vb, dW1, db1, eps, out_mu, out_lv, n);
    k_dec<<<eb, 128>>>(dW2, db2, dW3, db3, E);
    k_out<<<nb, 256>>>(out, n);
}

// round 8
// speedup vs baseline: 1.4914x; 1.4914x over previous
#include <cuda_runtime.h>
#include <math.h>

#define N_MAX 100000
typedef unsigned long long ull;
typedef unsigned int u32;

// ---- scratch (static __device__ arrays; allocation-free) ----
__device__ __align__(16) float g_A[N_MAX * 32];
__device__ __align__(16) float g_B[N_MAX * 32];
__device__ __align__(16) float g_sumenc[N_MAX * 4];
__device__ __align__(16) float g_cnt[N_MAX];
__device__ __align__(16) float g_sumout[N_MAX * 4];
__device__ __align__(16) float g_stats[8];

// ---- helpers ----
__device__ __forceinline__ ull pack2(float x, float y) {
    ull r; asm("mov.b64 %0, {%1,%2};" : "=l"(r) : "f"(x), "f"(y)); return r;
}
__device__ __forceinline__ void unpack2(ull v, float& x, float& y) {
    asm("mov.b64 {%0,%1}, %2;" : "=f"(x), "=f"(y) : "l"(v));
}
__device__ __forceinline__ void fma2(ull& d, ull a, ull b) {
    asm("fma.rn.f32x2 %0, %1, %2, %3;" : "=l"(d) : "l"(a), "l"(b), "l"(d));
}
__device__ __forceinline__ ull addp(ull a, ull b) {
    ull r; asm("add.rn.f32x2 %0, %1, %2;" : "=l"(r) : "l"(a), "l"(b)); return r;
}
__device__ __forceinline__ void red4(float* p, float a, float b, float c, float d) {
    asm volatile("red.global.add.v4.f32 [%0], {%1,%2,%3,%4};"
                 :: "l"(p), "f"(a), "f"(b), "f"(c), "f"(d) : "memory");
}
__device__ __forceinline__ void redf(float* p, float v) {
    asm volatile("red.global.add.f32 [%0], %1;" :: "l"(p), "f"(v) : "memory");
}
__device__ __forceinline__ ull shflx(ull v, int m) {
    return __shfl_xor_sync(0xffffffffu, v, m);
}
__device__ __forceinline__ u32 tf32r(float f) {
    u32 r; asm("cvt.rna.tf32.f32 %0, %1;" : "=r"(r) : "f"(f)); return r;
}
__device__ __forceinline__ void mma8(float* d, const u32* a, u32 b0, u32 b1) {
    asm volatile("mma.sync.aligned.m16n8k8.row.col.f32.tf32.tf32.f32 "
                 "{%0,%1,%2,%3},{%4,%5,%6,%7},{%8,%9},{%0,%1,%2,%3};"
                 : "+f"(d[0]), "+f"(d[1]), "+f"(d[2]), "+f"(d[3])
                 : "r"(a[0]), "r"(a[1]), "r"(a[2]), "r"(a[3]), "r"(b0), "r"(b1));
}

// ---- K0: zero accumulators ----
__global__ void k_zero(int n) {
    int i = blockIdx.x * blockDim.x + threadIdx.x;
    int stride = gridDim.x * blockDim.x;
    float4 z = make_float4(0.f, 0.f, 0.f, 0.f);
    float4* a = (float4*)g_sumenc; int na = n;
    for (int t = i; t < na; t += stride) a[t] = z;
    float4* b = (float4*)g_sumout; int nb = n;
    for (int t = i; t < nb; t += stride) b[t] = z;
    float4* c = (float4*)g_cnt;    int nc = n >> 2;
    for (int t = i; t < nc; t += stride) c[t] = z;
    if (i < 8) g_stats[i] = 0.f;
}

// ---- K1: batchnorm statistics ----
__global__ void k_stats(const float4* __restrict__ x, int n) {
    float sx = 0, sy = 0, sz = 0, sw = 0, qx = 0, qy = 0, qz = 0, qw = 0;
    for (int i = blockIdx.x * blockDim.x + threadIdx.x; i < n; i += gridDim.x * blockDim.x) {
        float4 v = x[i];
        sx += v.x; sy += v.y; sz += v.z; sw += v.w;
        qx += v.x * v.x; qy += v.y * v.y; qz += v.z * v.z; qw += v.w * v.w;
    }
    #pragma unroll
    for (int off = 16; off; off >>= 1) {
        sx += __shfl_down_sync(0xffffffffu, sx, off);
        sy += __shfl_down_sync(0xffffffffu, sy, off);
        sz += __shfl_down_sync(0xffffffffu, sz, off);
        sw += __shfl_down_sync(0xffffffffu, sw, off);
        qx += __shfl_down_sync(0xffffffffu, qx, off);
        qy += __shfl_down_sync(0xffffffffu, qy, off);
        qz += __shfl_down_sync(0xffffffffu, qz, off);
        qw += __shfl_down_sync(0xffffffffu, qw, off);
    }
    if ((threadIdx.x & 31) == 0) {
        atomicAdd(&g_stats[0], sx); atomicAdd(&g_stats[1], sy);
        atomicAdd(&g_stats[2], sz); atomicAdd(&g_stats[3], sw);
        atomicAdd(&g_stats[4], qx); atomicAdd(&g_stats[5], qy);
        atomicAdd(&g_stats[6], qz); atomicAdd(&g_stats[7], qw);
    }
}

// ---- K2: BN + encoder layer-1 split ----
__global__ void k_pre(const float4* __restrict__ x,
                      const float* __restrict__ gamma, const float* __restrict__ beta,
                      const float* __restrict__ eW1, const float* __restrict__ eb1,
                      int n, float invN) {
    __shared__ float sWd[128], sWb[128], sb1[32], sScale[4], sShift[4];
    int t = threadIdx.x;
    if (t < 128) {
        int c = t >> 5, o = t & 31;
        float wa = eW1[c * 32 + o], wb = eW1[(4 + c) * 32 + o];
        sWd[t] = wa - wb; sWb[t] = wb;
    }
    if (t < 32) sb1[t] = eb1[t];
    if (t < 4) {
        float m = g_stats[t] * invN;
        float v = g_stats[4 + t] * invN - m * m;
        float s = rsqrtf(v + 1e-5f) * gamma[t];
        sScale[t] = s; sShift[t] = beta[t] - m * s;
    }
    __syncthreads();
    for (int i = blockIdx.x * blockDim.x + t; i < n; i += gridDim.x * blockDim.x) {
        float4 xv = x[i];
        float xn[4];
        xn[0] = xv.x * sScale[0] + sShift[0];
        xn[1] = xv.y * sScale[1] + sShift[1];
        xn[2] = xv.z * sScale[2] + sShift[2];
        xn[3] = xv.w * sScale[3] + sShift[3];
        float a[32], b[32];
        #pragma unroll
        for (int o = 0; o < 32; o++) {
            float av = sb1[o], bv = 0.f;
            #pragma unroll
            for (int c = 0; c < 4; c++) {
                av += xn[c] * sWd[c * 32 + o];
                bv += xn[c] * sWb[c * 32 + o];
            }
            a[o] = av; b[o] = bv;
        }
        float4* Ao = (float4*)(g_A + (size_t)i * 32);
        float4* Bo = (float4*)(g_B + (size_t)i * 32);
        #pragma unroll
        for (int q = 0; q < 8; q++) {
            Ao[q] = make_float4(a[4*q], a[4*q+1], a[4*q+2], a[4*q+3]);
            Bo[q] = make_float4(b[4*q], b[4*q+1], b[4*q+2], b[4*q+3]);
        }
    }
}

// ---- shared gather-to-smem step: quad layout, 16 edges per pass ----
// lane (qid,qlane); stores u rows (stride 36 floats) into myU
__device__ __forceinline__ void gather_pass(const int* __restrict__ ei, int E,
                                            int e0, int qlane, float* rowp) {
    int e1 = e0 + 1;
    bool v0 = e0 < E, v1 = e1 < E;
    int src0 = 0, tgt0 = 0, src1 = 0, tgt1 = 0;
    if (v1) {
        int2 s  = *(const int2*)(ei + e0);
        int2 t2 = *(const int2*)(ei + E + e0);
        src0 = s.x; src1 = s.y; tgt0 = t2.x; tgt1 = t2.y;
    } else if (v0) {
        src0 = ei[e0]; tgt0 = ei[E + e0];
    }
    const float4* Ar0 = (const float4*)(g_A + (size_t)tgt0 * 32);
    const float4* Br0 = (const float4*)(g_B + (size_t)src0 * 32);
    const float4* Ar1 = (const float4*)(g_A + (size_t)tgt1 * 32);
    const float4* Br1 = (const float4*)(g_B + (size_t)src1 * 32);
    float4 z = make_float4(0.f, 0.f, 0.f, 0.f);
    float4 al0 = z, ah0 = z, bl0 = z, bh0 = z, al1 = z, ah1 = z, bl1 = z, bh1 = z;
    if (v0) { al0 = __ldg(Ar0 + qlane); ah0 = __ldg(Ar0 + 4 + qlane);
              bl0 = __ldg(Br0 + qlane); bh0 = __ldg(Br0 + 4 + qlane); }
    if (v1) { al1 = __ldg(Ar1 + qlane); ah1 = __ldg(Ar1 + 4 + qlane);
              bl1 = __ldg(Br1 + qlane); bh1 = __ldg(Br1 + 4 + qlane); }
    // u = relu(A[tgt] + B[src]); rows e0, e0+1; cols 4q..4q+3 and 16+4q..+3
    *(float4*)(rowp) = make_float4(
        fmaxf(al0.x + bl0.x, 0.f), fmaxf(al0.y + bl0.y, 0.f),
        fmaxf(al0.z + bl0.z, 0.f), fmaxf(al0.w + bl0.w, 0.f));
    *(float4*)(rowp + 16) = make_float4(
        fmaxf(ah0.x + bh0.x, 0.f), fmaxf(ah0.y + bh0.y, 0.f),
        fmaxf(ah0.z + bh0.z, 0.f), fmaxf(ah0.w + bh0.w, 0.f));
    *(float4*)(rowp + 36) = make_float4(
        fmaxf(al1.x + bl1.x, 0.f), fmaxf(al1.y + bl1.y, 0.f),
        fmaxf(al1.z + bl1.z, 0.f), fmaxf(al1.w + bl1.w, 0.f));
    *(float4*)(rowp + 36 + 16) = make_float4(
        fmaxf(ah1.x + bh1.x, 0.f), fmaxf(ah1.y + bh1.y, 0.f),
        fmaxf(ah1.z + bh1.z, 0.f), fmaxf(ah1.w + bh1.w, 0.f));
}

// ===================== encoder: MMA(tf32 3-term) + projected epilogue =====================
__global__ void __launch_bounds__(128, 4) k_enc(const int* __restrict__ ei,
                                                const float* __restrict__ W2,
                                                const float* __restrict__ b2,
                                                const float* __restrict__ mW,
                                                const float* __restrict__ vW, int E) {
    __shared__ __align__(16) float sU[4][32 * 36];
    __shared__ u32 sBl[32 * 40];

    // Bl (low-order tf32 residual of W2) into smem, stride 40 (conflict-free frag loads)
    for (int idx = threadIdx.x; idx < 1024; idx += 128) {
        float w = W2[idx];
        u32 wh = tf32r(w);
        sBl[(idx >> 5) * 40 + (idx & 31)] = tf32r(w - __uint_as_float(wh));
    }
    __syncthreads();

    int lane = threadIdx.x & 31, warp = threadIdx.x >> 5;
    int g_ = lane >> 2, c_ = lane & 3;
    int qid = lane >> 2, qlane = lane & 3;

    // Bh (high tf32 of W2) in registers: [kt][nt][2]
    u32 bh[4][4][2];
    #pragma unroll
    for (int kt = 0; kt < 4; kt++)
        #pragma unroll
        for (int nt = 0; nt < 4; nt++) {
            bh[kt][nt][0] = tf32r(W2[(kt * 8 + c_) * 32 + nt * 8 + g_]);
            bh[kt][nt][1] = tf32r(W2[(kt * 8 + c_ + 4) * 32 + nt * 8 + g_]);
        }
    // bias columns owned by this lane
    float b20[4], b21[4];
    #pragma unroll
    for (int nt = 0; nt < 4; nt++) {
        b20[nt] = b2[nt * 8 + 2 * c_];
        b21[nt] = b2[nt * 8 + 2 * c_ + 1];
    }

    int tb = (blockIdx.x * 4 + warp) * 32;
    if (tb >= E) return;
    float* myU = &sU[warp][0];

    // gather 2 passes of 16 edges into smem u-tile
    #pragma unroll
    for (int P = 0; P < 2; P++) {
        int e0 = tb + 16 * P + 2 * qid;
        float* rowp = myU + (16 * P + 2 * qid) * 36 + 4 * qlane;
        gather_pass(ei, E, e0, qlane, rowp);
    }
    __syncwarp();

    #pragma unroll
    for (int mt = 0; mt < 2; mt++) {
        const float* ub = myU + mt * 16 * 36;
        u32 ah[4][4], al[4][4];
        #pragma unroll
        for (int kt = 0; kt < 4; kt++) {
            float a0 = ub[g_ * 36 + kt * 8 + c_];
            float a1 = ub[(g_ + 8) * 36 + kt * 8 + c_];
            float a2 = ub[g_ * 36 + kt * 8 + c_ + 4];
            float a3 = ub[(g_ + 8) * 36 + kt * 8 + c_ + 4];
            ah[kt][0] = tf32r(a0); al[kt][0] = tf32r(a0 - __uint_as_float(ah[kt][0]));
            ah[kt][1] = tf32r(a1); al[kt][1] = tf32r(a1 - __uint_as_float(ah[kt][1]));
            ah[kt][2] = tf32r(a2); al[kt][2] = tf32r(a2 - __uint_as_float(ah[kt][2]));
            ah[kt][3] = tf32r(a3); al[kt][3] = tf32r(a3 - __uint_as_float(ah[kt][3]));
        }
        float d[4][4];
        #pragma unroll
        for (int nt = 0; nt < 4; nt++)
            #pragma unroll
            for (int j = 0; j < 4; j++) d[nt][j] = 0.f;
        #pragma unroll
        for (int nt = 0; nt < 4; nt++)
            #pragma unroll
            for (int kt = 0; kt < 4; kt++) {
                mma8(d[nt], ah[kt], bh[kt][nt][0], bh[kt][nt][1]);
                mma8(d[nt], al[kt], bh[kt][nt][0], bh[kt][nt][1]);
                u32 bl0 = sBl[(kt * 8 + c_) * 40 + nt * 8 + g_];
                u32 bl1 = sBl[(kt * 8 + c_ + 4) * 40 + nt * 8 + g_];
                mma8(d[nt], ah[kt], bl0, bl1);
            }

        // epilogue: msg=relu(d+b2); project to [mW|vW]; quad-reduce over c_
        ull p01_0 = 0, p23_0 = 0, p01_1 = 0, p23_1 = 0;
        #pragma unroll
        for (int nt = 0; nt < 4; nt++) {
            int col0 = nt * 8 + 2 * c_;
            float m00 = fmaxf(d[nt][0] + b20[nt], 0.f);
            float m01 = fmaxf(d[nt][1] + b21[nt], 0.f);
            float m10 = fmaxf(d[nt][2] + b20[nt], 0.f);
            float m11 = fmaxf(d[nt][3] + b21[nt], 0.f);
            ull qm0 = *(const ull*)(mW + (size_t)col0 * 2);
            ull qv0 = *(const ull*)(vW + (size_t)col0 * 2);
            ull qm1 = *(const ull*)(mW + (size_t)col0 * 2 + 2);
            ull qv1 = *(const ull*)(vW + (size_t)col0 * 2 + 2);
            fma2(p01_0, pack2(m00, m00), qm0); fma2(p23_0, pack2(m00, m00), qv0);
            fma2(p01_0, pack2(m01, m01), qm1); fma2(p23_0, pack2(m01, m01), qv1);
            fma2(p01_1, pack2(m10, m10), qm0); fma2(p23_1, pack2(m10, m10), qv0);
            fma2(p01_1, pack2(m11, m11), qm1); fma2(p23_1, pack2(m11, m11), qv1);
        }
        p01_0 = addp(p01_0, shflx(p01_0, 1)); p01_0 = addp(p01_0, shflx(p01_0, 2));
        p23_0 = addp(p23_0, shflx(p23_0, 1)); p23_0 = addp(p23_0, shflx(p23_0, 2));
        p01_1 = addp(p01_1, shflx(p01_1, 1)); p01_1 = addp(p01_1, shflx(p01_1, 2));
        p23_1 = addp(p23_1, shflx(p23_1, 1)); p23_1 = addp(p23_1, shflx(p23_1, 2));

        if (c_ == 0) {
            int ea = tb + mt * 16 + g_;
            int eb_ = ea + 8;
            if (ea < E) {
                int tg = ei[E + ea];
                float f0, f1, f2, f3;
                unpack2(p01_0, f0, f1); unpack2(p23_0, f2, f3);
                red4(g_sumenc + (size_t)tg * 4, f0, f1, f2, f3);
                redf(&g_cnt[tg], 1.0f);
            }
            if (eb_ < E) {
                int tg = ei[E + eb_];
                float f0, f1, f2, f3;
                unpack2(p01_1, f0, f1); unpack2(p23_1, f2, f3);
                red4(g_sumenc + (size_t)tg * 4, f0, f1, f2, f3);
                redf(&g_cnt[tg], 1.0f);
            }
        }
    }
}

// ---- K4: per-node mid ----
__global__ void k_mid(const float* __restrict__ mb, const float* __restrict__ vb,
                      const float* __restrict__ dW1, const float* __restrict__ db1,
                      const float* __restrict__ eps2,
                      float* __restrict__ out_mu, float* __restrict__ out_lv, int n) {
    __shared__ float sWd[64], sWb[64], sdb1[32], smb[2], svb[2];
    int t = threadIdx.x;
    if (t < 32) {
        sdb1[t] = db1[t];
        sWd[t]      = dW1[t]      - dW1[64 + t];
        sWd[32 + t] = dW1[32 + t] - dW1[96 + t];
        sWb[t]      = dW1[64 + t];
        sWb[32 + t] = dW1[96 + t];
    }
    if (t < 2) { smb[t] = mb[t]; svb[t] = vb[t]; }
    __syncthreads();
    for (int i = blockIdx.x * blockDim.x + t; i < n; i += gridDim.x * blockDim.x) {
        float4 s = ((const float4*)g_sumenc)[i];
        float inv = 1.0f / fmaxf(g_cnt[i], 1.0f);
        float mu0 = s.x * inv + smb[0];
        float mu1 = s.y * inv + smb[1];
        float lv0 = s.z * inv + svb[0];
        float lv1 = s.w * inv + svb[1];
        float2 ep = ((const float2*)eps2)[i];
        float z0 = mu0 + ep.x * expf(0.5f * lv0);
        float z1 = mu1 + ep.y * expf(0.5f * lv1);
        ((float2*)out_mu)[i] = make_float2(mu0, mu1);
        ((float2*)out_lv)[i] = make_float2(lv0, lv1);
        float a[32], b[32];
        #pragma unroll
        for (int o = 0; o < 32; o++) {
            a[o] = sdb1[o] + z0 * sWd[o] + z1 * sWd[32 + o];
            b[o] = z0 * sWb[o] + z1 * sWb[32 + o];
        }
        float4* Ao = (float4*)(g_A + (size_t)i * 32);
        float4* Bo = (float4*)(g_B + (size_t)i * 32);
        #pragma unroll
        for (int q = 0; q < 8; q++) {
            Ao[q] = make_float4(a[4*q], a[4*q+1], a[4*q+2], a[4*q+3]);
            Bo[q] = make_float4(b[4*q], b[4*q+1], b[4*q+2], b[4*q+3]);
        }
    }
}

// ===================== decoder: MMA(tf32 3-term) + W3 epilogue =====================
__global__ void __launch_bounds__(128, 4) k_dec(const int* __restrict__ ei,
                                                const float* __restrict__ W2,
                                                const float* __restrict__ b2,
                                                const float* __restrict__ W3,
                                                const float* __restrict__ b3, int E) {
    __shared__ __align__(16) float sU[4][32 * 36];
    __shared__ u32 sBl[32 * 40];

    for (int idx = threadIdx.x; idx < 1024; idx += 128) {
        float w = W2[idx];
        u32 wh = tf32r(w);
        sBl[(idx >> 5) * 40 + (idx & 31)] = tf32r(w - __uint_as_float(wh));
    }
    __syncthreads();

    int lane = threadIdx.x & 31, warp = threadIdx.x >> 5;
    int g_ = lane >> 2, c_ = lane & 3;
    int qid = lane >> 2, qlane = lane & 3;

    u32 bh[4][4][2];
    #pragma unroll
    for (int kt = 0; kt < 4; kt++)
        #pragma unroll
        for (int nt = 0; nt < 4; nt++) {
            bh[kt][nt][0] = tf32r(W2[(kt * 8 + c_) * 32 + nt * 8 + g_]);
            bh[kt][nt][1] = tf32r(W2[(kt * 8 + c_ + 4) * 32 + nt * 8 + g_]);
        }
    float b20[4], b21[4];
    #pragma unroll
    for (int nt = 0; nt < 4; nt++) {
        b20[nt] = b2[nt * 8 + 2 * c_];
        b21[nt] = b2[nt * 8 + 2 * c_ + 1];
    }
    ull b3a = *(const ull*)(b3);
    ull b3b = *(const ull*)(b3 + 2);

    int tb = (blockIdx.x * 4 + warp) * 32;
    if (tb >= E) return;
    float* myU = &sU[warp][0];

    #pragma unroll
    for (int P = 0; P < 2; P++) {
        int e0 = tb + 16 * P + 2 * qid;
        float* rowp = myU + (16 * P + 2 * qid) * 36 + 4 * qlane;
        gather_pass(ei, E, e0, qlane, rowp);
    }
    __syncwarp();

    #pragma unroll
    for (int mt = 0; mt < 2; mt++) {
        const float* ub = myU + mt * 16 * 36;
        u32 ah[4][4], al[4][4];
        #pragma unroll
        for (int kt = 0; kt < 4; kt++) {
            float a0 = ub[g_ * 36 + kt * 8 + c_];
            float a1 = ub[(g_ + 8) * 36 + kt * 8 + c_];
            float a2 = ub[g_ * 36 + kt * 8 + c_ + 4];
            float a3 = ub[(g_ + 8) * 36 + kt * 8 + c_ + 4];
            ah[kt][0] = tf32r(a0); al[kt][0] = tf32r(a0 - __uint_as_float(ah[kt][0]));
            ah[kt][1] = tf32r(a1); al[kt][1] = tf32r(a1 - __uint_as_float(ah[kt][1]));
            ah[kt][2] = tf32r(a2); al[kt][2] = tf32r(a2 - __uint_as_float(ah[kt][2]));
            ah[kt][3] = tf32r(a3); al[kt][3] = tf32r(a3 - __uint_as_float(ah[kt][3]));
        }
        float d[4][4];
        #pragma unroll
        for (int nt = 0; nt < 4; nt++)
            #pragma unroll
            for (int j = 0; j < 4; j++) d[nt][j] = 0.f;
        #pragma unroll
        for (int nt = 0; nt < 4; nt++)
            #pragma unroll
            for (int kt = 0; kt < 4; kt++) {
                mma8(d[nt], ah[kt], bh[kt][nt][0], bh[kt][nt][1]);
                mma8(d[nt], al[kt], bh[kt][nt][0], bh[kt][nt][1]);
                u32 bl0 = sBl[(kt * 8 + c_) * 40 + nt * 8 + g_];
                u32 bl1 = sBl[(kt * 8 + c_ + 4) * 40 + nt * 8 + g_];
                mma8(d[nt], ah[kt], bl0, bl1);
            }

        // epilogue: v=relu(d+b2); out4 = v@W3 (+b3 after reduce)
        ull o01_0 = 0, o23_0 = 0, o01_1 = 0, o23_1 = 0;
        #pragma unroll
        for (int nt = 0; nt < 4; nt++) {
            int col0 = nt * 8 + 2 * c_;
            float m00 = fmaxf(d[nt][0] + b20[nt], 0.f);
            float m01 = fmaxf(d[nt][1] + b21[nt], 0.f);
            float m10 = fmaxf(d[nt][2] + b20[nt], 0.f);
            float m11 = fmaxf(d[nt][3] + b21[nt], 0.f);
            ull w01a = *(const ull*)(W3 + (size_t)col0 * 4);
            ull w23a = *(const ull*)(W3 + (size_t)col0 * 4 + 2);
            ull w01b = *(const ull*)(W3 + (size_t)(col0 + 1) * 4);
            ull w23b = *(const ull*)(W3 + (size_t)(col0 + 1) * 4 + 2);
            fma2(o01_0, pack2(m00, m00), w01a); fma2(o23_0, pack2(m00, m00), w23a);
            fma2(o01_0, pack2(m01, m01), w01b); fma2(o23_0, pack2(m01, m01), w23b);
            fma2(o01_1, pack2(m10, m10), w01a); fma2(o23_1, pack2(m10, m10), w23a);
            fma2(o01_1, pack2(m11, m11), w01b); fma2(o23_1, pack2(m11, m11), w23b);
        }
        o01_0 = addp(o01_0, shflx(o01_0, 1)); o01_0 = addp(o01_0, shflx(o01_0, 2));
        o23_0 = addp(o23_0, shflx(o23_0, 1)); o23_0 = addp(o23_0, shflx(o23_0, 2));
        o01_1 = addp(o01_1, shflx(o01_1, 1)); o01_1 = addp(o01_1, shflx(o01_1, 2));
        o23_1 = addp(o23_1, shflx(o23_1, 1)); o23_1 = addp(o23_1, shflx(o23_1, 2));

        if (c_ == 0) {
            int ea = tb + mt * 16 + g_;
            int eb_ = ea + 8;
            if (ea < E) {
                int tg = ei[E + ea];
                ull r0 = addp(o01_0, b3a), r1 = addp(o23_0, b3b);
                float f0, f1, f2, f3;
                unpack2(r0, f0, f1); unpack2(r1, f2, f3);
                red4(g_sumout + (size_t)tg * 4, f0, f1, f2, f3);
            }
            if (eb_ < E) {
                int tg = ei[E + eb_];
                ull r0 = addp(o01_1, b3a), r1 = addp(o23_1, b3b);
                float f0, f1, f2, f3;
                unpack2(r0, f0, f1); unpack2(r1, f2, f3);
                red4(g_sumout + (size_t)tg * 4, f0, f1, f2, f3);
            }
        }
    }
}

// ---- K6: per-node output mean ----
__global__ void k_out(float* __restrict__ out, int n) {
    for (int i = blockIdx.x * blockDim.x + threadIdx.x; i < n; i += gridDim.x * blockDim.x) {
        float inv = 1.0f / fmaxf(g_cnt[i], 1.0f);
        float4 s = ((const float4*)g_sumout)[i];
        ((float4*)out)[i] = make_float4(s.x * inv, s.y * inv, s.z * inv, s.w * inv);
    }
}

extern "C" void kernel_launch(void* const* d_in, const int* in_sizes, int n_in,
                              void* d_out, int out_size) {
    const float* x     = (const float*)d_in[0];
    const int*   ei    = (const int*)d_in[1];
    const float* eps   = (const float*)d_in[2];
    const float* gamma = (const float*)d_in[3];
    const float* beta  = (const float*)d_in[4];
    const float* eW1   = (const float*)d_in[5];
    const float* eb1   = (const float*)d_in[6];
    const float* eW2   = (const float*)d_in[7];
    const float* eb2   = (const float*)d_in[8];
    const float* mW    = (const float*)d_in[9];
    const float* mb    = (const float*)d_in[10];
    const float* vW    = (const float*)d_in[11];
    const float* vb    = (const float*)d_in[12];
    const float* dW1   = (const float*)d_in[13];
    const float* db1   = (const float*)d_in[14];
    const float* dW2   = (const float*)d_in[15];
    const float* db2   = (const float*)d_in[16];
    const float* dW3   = (const float*)d_in[17];
    const float* db3   = (const float*)d_in[18];

    int n = in_sizes[0] / 4;
    int E = in_sizes[1] / 2;

    float* out    = (float*)d_out;
    float* out_mu = out + (size_t)n * 4;
    float* out_lv = out + (size_t)n * 6;

    int nb = (n + 255) / 256;
    int eb = (E + 127) / 128;   // 128 edges per block (4 warps x 32-edge MMA tiles)

    k_zero<<<256, 256>>>(n);
    k_stats<<<256, 256>>>((const float4*)x, n);
    k_pre<<<nb, 256>>>((const float4*)x, gamma, beta, eW1, eb1, n, 1.0f / (float)n);
    k_enc<<<eb, 128>>>(ei, eW2, eb2, mW, vW, E);
    k_mid<<<nb, 256>>>(mb, vb, dW1, db1, eps, out_mu, out_lv, n);
    k_dec<<<eb, 128>>>(ei, dW2, db2, dW3, db3, E);
    k_out<<<nb, 256>>>(out, n);
}

// round 9
// speedup vs baseline: 1.7781x; 1.1922x over previous
#include <cuda_runtime.h>
#include <math.h>

#define N_MAX 100000
typedef unsigned long long ull;
typedef unsigned int u32;

// ---- scratch (static __device__ arrays; allocation-free) ----
__device__ __align__(16) float g_A[N_MAX * 32];
__device__ __align__(16) float g_B[N_MAX * 32];
__device__ __align__(16) float g_sumenc[N_MAX * 4];
__device__ __align__(16) float g_cnt[N_MAX];
__device__ __align__(16) float g_sumout[N_MAX * 4];
__device__ __align__(16) float g_stats[8];

// ---- helpers ----
__device__ __forceinline__ ull pack2(float x, float y) {
    ull r; asm("mov.b64 %0, {%1,%2};" : "=l"(r) : "f"(x), "f"(y)); return r;
}
__device__ __forceinline__ void unpack2(ull v, float& x, float& y) {
    asm("mov.b64 {%0,%1}, %2;" : "=f"(x), "=f"(y) : "l"(v));
}
__device__ __forceinline__ void fma2(ull& d, ull a, ull b) {
    asm("fma.rn.f32x2 %0, %1, %2, %3;" : "=l"(d) : "l"(a), "l"(b), "l"(d));
}
__device__ __forceinline__ ull addp(ull a, ull b) {
    ull r; asm("add.rn.f32x2 %0, %1, %2;" : "=l"(r) : "l"(a), "l"(b)); return r;
}
__device__ __forceinline__ void red4(float* p, float a, float b, float c, float d) {
    asm volatile("red.global.add.v4.f32 [%0], {%1,%2,%3,%4};"
                 :: "l"(p), "f"(a), "f"(b), "f"(c), "f"(d) : "memory");
}
__device__ __forceinline__ void redf(float* p, float v) {
    asm volatile("red.global.add.f32 [%0], %1;" :: "l"(p), "f"(v) : "memory");
}
__device__ __forceinline__ ull shflx(ull v, int m) {
    return __shfl_xor_sync(0xffffffffu, v, m);
}
__device__ __forceinline__ u32 tf32r(float f) {
    u32 r; asm("cvt.rna.tf32.f32 %0, %1;" : "=r"(r) : "f"(f)); return r;
}
__device__ __forceinline__ void mma8(float* d, const u32* a, u32 b0, u32 b1) {
    asm volatile("mma.sync.aligned.m16n8k8.row.col.f32.tf32.tf32.f32 "
                 "{%0,%1,%2,%3},{%4,%5,%6,%7},{%8,%9},{%0,%1,%2,%3};"
                 : "+f"(d[0]), "+f"(d[1]), "+f"(d[2]), "+f"(d[3])
                 : "r"(a[0]), "r"(a[1]), "r"(a[2]), "r"(a[3]), "r"(b0), "r"(b1));
}
__device__ __forceinline__ void lds64(unsigned addr, u32& a, u32& b) {
    asm volatile("ld.shared.v2.u32 {%0,%1}, [%2];" : "=r"(a), "=r"(b) : "r"(addr));
}

// ---- K0: zero accumulators ----
__global__ void k_zero(int n) {
    int i = blockIdx.x * blockDim.x + threadIdx.x;
    int stride = gridDim.x * blockDim.x;
    float4 z = make_float4(0.f, 0.f, 0.f, 0.f);
    float4* a = (float4*)g_sumenc; int na = n;
    for (int t = i; t < na; t += stride) a[t] = z;
    float4* b = (float4*)g_sumout; int nb = n;
    for (int t = i; t < nb; t += stride) b[t] = z;
    float4* c = (float4*)g_cnt;    int nc = n >> 2;
    for (int t = i; t < nc; t += stride) c[t] = z;
    if (i < 8) g_stats[i] = 0.f;
}

// ---- K1: batchnorm statistics ----
__global__ void k_stats(const float4* __restrict__ x, int n) {
    float sx = 0, sy = 0, sz = 0, sw = 0, qx = 0, qy = 0, qz = 0, qw = 0;
    for (int i = blockIdx.x * blockDim.x + threadIdx.x; i < n; i += gridDim.x * blockDim.x) {
        float4 v = x[i];
        sx += v.x; sy += v.y; sz += v.z; sw += v.w;
        qx += v.x * v.x; qy += v.y * v.y; qz += v.z * v.z; qw += v.w * v.w;
    }
    #pragma unroll
    for (int off = 16; off; off >>= 1) {
        sx += __shfl_down_sync(0xffffffffu, sx, off);
        sy += __shfl_down_sync(0xffffffffu, sy, off);
        sz += __shfl_down_sync(0xffffffffu, sz, off);
        sw += __shfl_down_sync(0xffffffffu, sw, off);
        qx += __shfl_down_sync(0xffffffffu, qx, off);
        qy += __shfl_down_sync(0xffffffffu, qy, off);
        qz += __shfl_down_sync(0xffffffffu, qz, off);
        qw += __shfl_down_sync(0xffffffffu, qw, off);
    }
    if ((threadIdx.x & 31) == 0) {
        atomicAdd(&g_stats[0], sx); atomicAdd(&g_stats[1], sy);
        atomicAdd(&g_stats[2], sz); atomicAdd(&g_stats[3], sw);
        atomicAdd(&g_stats[4], qx); atomicAdd(&g_stats[5], qy);
        atomicAdd(&g_stats[6], qz); atomicAdd(&g_stats[7], qw);
    }
}

// ---- K2: BN + encoder layer-1 split ----
__global__ void k_pre(const float4* __restrict__ x,
                      const float* __restrict__ gamma, const float* __restrict__ beta,
                      const float* __restrict__ eW1, const float* __restrict__ eb1,
                      int n, float invN) {
    __shared__ float sWd[128], sWb[128], sb1[32], sScale[4], sShift[4];
    int t = threadIdx.x;
    if (t < 128) {
        int c = t >> 5, o = t & 31;
        float wa = eW1[c * 32 + o], wb = eW1[(4 + c) * 32 + o];
        sWd[t] = wa - wb; sWb[t] = wb;
    }
    if (t < 32) sb1[t] = eb1[t];
    if (t < 4) {
        float m = g_stats[t] * invN;
        float v = g_stats[4 + t] * invN - m * m;
        float s = rsqrtf(v + 1e-5f) * gamma[t];
        sScale[t] = s; sShift[t] = beta[t] - m * s;
    }
    __syncthreads();
    for (int i = blockIdx.x * blockDim.x + t; i < n; i += gridDim.x * blockDim.x) {
        float4 xv = x[i];
        float xn[4];
        xn[0] = xv.x * sScale[0] + sShift[0];
        xn[1] = xv.y * sScale[1] + sShift[1];
        xn[2] = xv.z * sScale[2] + sShift[2];
        xn[3] = xv.w * sScale[3] + sShift[3];
        float a[32], b[32];
        #pragma unroll
        for (int o = 0; o < 32; o++) {
            float av = sb1[o], bv = 0.f;
            #pragma unroll
            for (int c = 0; c < 4; c++) {
                av += xn[c] * sWd[c * 32 + o];
                bv += xn[c] * sWb[c * 32 + o];
            }
            a[o] = av; b[o] = bv;
        }
        float4* Ao = (float4*)(g_A + (size_t)i * 32);
        float4* Bo = (float4*)(g_B + (size_t)i * 32);
        #pragma unroll
        for (int q = 0; q < 8; q++) {
            Ao[q] = make_float4(a[4*q], a[4*q+1], a[4*q+2], a[4*q+3]);
            Bo[q] = make_float4(b[4*q], b[4*q+1], b[4*q+2], b[4*q+3]);
        }
    }
}

// ---- gather (full tile, no bounds checks) ----
__device__ __forceinline__ void gather_full(const int* __restrict__ ei, int E,
                                            int e0, int qlane, float* rowp) {
    int2 s  = *(const int2*)(ei + e0);
    int2 t2 = *(const int2*)(ei + E + e0);
    const float4* Ar0 = (const float4*)(g_A + (size_t)t2.x * 32);
    const float4* Br0 = (const float4*)(g_B + (size_t)s.x * 32);
    const float4* Ar1 = (const float4*)(g_A + (size_t)t2.y * 32);
    const float4* Br1 = (const float4*)(g_B + (size_t)s.y * 32);
    float4 al0 = __ldg(Ar0 + qlane), ah0 = __ldg(Ar0 + 4 + qlane);
    float4 bl0 = __ldg(Br0 + qlane), bh0 = __ldg(Br0 + 4 + qlane);
    float4 al1 = __ldg(Ar1 + qlane), ah1 = __ldg(Ar1 + 4 + qlane);
    float4 bl1 = __ldg(Br1 + qlane), bh1 = __ldg(Br1 + 4 + qlane);
    *(float4*)(rowp) = make_float4(
        fmaxf(al0.x + bl0.x, 0.f), fmaxf(al0.y + bl0.y, 0.f),
        fmaxf(al0.z + bl0.z, 0.f), fmaxf(al0.w + bl0.w, 0.f));
    *(float4*)(rowp + 16) = make_float4(
        fmaxf(ah0.x + bh0.x, 0.f), fmaxf(ah0.y + bh0.y, 0.f),
        fmaxf(ah0.z + bh0.z, 0.f), fmaxf(ah0.w + bh0.w, 0.f));
    *(float4*)(rowp + 36) = make_float4(
        fmaxf(al1.x + bl1.x, 0.f), fmaxf(al1.y + bl1.y, 0.f),
        fmaxf(al1.z + bl1.z, 0.f), fmaxf(al1.w + bl1.w, 0.f));
    *(float4*)(rowp + 36 + 16) = make_float4(
        fmaxf(ah1.x + bh1.x, 0.f), fmaxf(ah1.y + bh1.y, 0.f),
        fmaxf(ah1.z + bh1.z, 0.f), fmaxf(ah1.w + bh1.w, 0.f));
}

// ---- gather (tail, with bounds checks) ----
__device__ __forceinline__ void gather_tail(const int* __restrict__ ei, int E,
                                            int e0, int qlane, float* rowp) {
    int e1 = e0 + 1;
    bool v0 = e0 < E, v1 = e1 < E;
    int src0 = 0, tgt0 = 0, src1 = 0, tgt1 = 0;
    if (v1) {
        int2 s  = *(const int2*)(ei + e0);
        int2 t2 = *(const int2*)(ei + E + e0);
        src0 = s.x; src1 = s.y; tgt0 = t2.x; tgt1 = t2.y;
    } else if (v0) {
        src0 = ei[e0]; tgt0 = ei[E + e0];
    }
    const float4* Ar0 = (const float4*)(g_A + (size_t)tgt0 * 32);
    const float4* Br0 = (const float4*)(g_B + (size_t)src0 * 32);
    const float4* Ar1 = (const float4*)(g_A + (size_t)tgt1 * 32);
    const float4* Br1 = (const float4*)(g_B + (size_t)src1 * 32);
    float4 z = make_float4(0.f, 0.f, 0.f, 0.f);
    float4 al0 = z, ah0 = z, bl0 = z, bh0 = z, al1 = z, ah1 = z, bl1 = z, bh1 = z;
    if (v0) { al0 = __ldg(Ar0 + qlane); ah0 = __ldg(Ar0 + 4 + qlane);
              bl0 = __ldg(Br0 + qlane); bh0 = __ldg(Br0 + 4 + qlane); }
    if (v1) { al1 = __ldg(Ar1 + qlane); ah1 = __ldg(Ar1 + 4 + qlane);
              bl1 = __ldg(Br1 + qlane); bh1 = __ldg(Br1 + 4 + qlane); }
    *(float4*)(rowp) = make_float4(
        fmaxf(al0.x + bl0.x, 0.f), fmaxf(al0.y + bl0.y, 0.f),
        fmaxf(al0.z + bl0.z, 0.f), fmaxf(al0.w + bl0.w, 0.f));
    *(float4*)(rowp + 16) = make_float4(
        fmaxf(ah0.x + bh0.x, 0.f), fmaxf(ah0.y + bh0.y, 0.f),
        fmaxf(ah0.z + bh0.z, 0.f), fmaxf(ah0.w + bh0.w, 0.f));
    *(float4*)(rowp + 36) = make_float4(
        fmaxf(al1.x + bl1.x, 0.f), fmaxf(al1.y + bl1.y, 0.f),
        fmaxf(al1.z + bl1.z, 0.f), fmaxf(al1.w + bl1.w, 0.f));
    *(float4*)(rowp + 36 + 16) = make_float4(
        fmaxf(ah1.x + bh1.x, 0.f), fmaxf(ah1.y + bh1.y, 0.f),
        fmaxf(ah1.z + bh1.z, 0.f), fmaxf(ah1.w + bh1.w, 0.f));
}

// ---- shared: fill paired Bh/Bl smem tiles from a 32x32 weight matrix ----
// slot(kt,nt,g,c) at byte offset ((kt*4+nt)*32 + g*4 + c) * 8, holding {row kt*8+c, row kt*8+c+4} at col nt*8+g
__device__ __forceinline__ void fill_B(const float* __restrict__ W, u32* sBh, u32* sBl) {
    for (int idx = threadIdx.x; idx < 512; idx += 128) {
        int kt = idx >> 7, nt = (idx >> 5) & 3, gg = (idx >> 2) & 7, cc = idx & 3;
        float w0 = W[(kt * 8 + cc) * 32 + nt * 8 + gg];
        float w1 = W[(kt * 8 + cc + 4) * 32 + nt * 8 + gg];
        u32 h0 = tf32r(w0), h1 = tf32r(w1);
        int slot = ((kt * 4 + nt) * 32 + gg * 4 + cc) * 2;
        sBh[slot] = h0; sBh[slot + 1] = h1;
        sBl[slot] = tf32r(w0 - __uint_as_float(h0));
        sBl[slot + 1] = tf32r(w1 - __uint_as_float(h1));
    }
}

// ---- shared: 3-term tf32 MMA of one 16x32 u-tile against smem B ----
__device__ __forceinline__ void mma_tile(const float* ub, int g_, int c_,
                                         unsigned bhb, unsigned blb, float d[4][4]) {
    #pragma unroll
    for (int nt = 0; nt < 4; nt++)
        #pragma unroll
        for (int j = 0; j < 4; j++) d[nt][j] = 0.f;
    #pragma unroll
    for (int kt = 0; kt < 4; kt++) {
        float a0 = ub[g_ * 36 + kt * 8 + c_];
        float a1 = ub[(g_ + 8) * 36 + kt * 8 + c_];
        float a2 = ub[g_ * 36 + kt * 8 + c_ + 4];
        float a3 = ub[(g_ + 8) * 36 + kt * 8 + c_ + 4];
        u32 ah[4], al[4];
        ah[0] = tf32r(a0); al[0] = tf32r(a0 - __uint_as_float(ah[0]));
        ah[1] = tf32r(a1); al[1] = tf32r(a1 - __uint_as_float(ah[1]));
        ah[2] = tf32r(a2); al[2] = tf32r(a2 - __uint_as_float(ah[2]));
        ah[3] = tf32r(a3); al[3] = tf32r(a3 - __uint_as_float(ah[3]));
        #pragma unroll
        for (int nt = 0; nt < 4; nt++) {
            unsigned off = (unsigned)(kt * 4 + nt) * 256u;
            u32 b0, b1, l0, l1;
            lds64(bhb + off, b0, b1);
            lds64(blb + off, l0, l1);
            mma8(d[nt], ah, b0, b1);
            mma8(d[nt], al, b0, b1);
            mma8(d[nt], ah, l0, l1);
        }
    }
}

// ===================== encoder: MMA(tf32 3-term) + projected epilogue =====================
__global__ void __launch_bounds__(128, 6) k_enc(const int* __restrict__ ei,
                                                const float* __restrict__ W2,
                                                const float* __restrict__ b2,
                                                const float* __restrict__ mW,
                                                const float* __restrict__ vW, int E) {
    __shared__ __align__(16) float sU[4][32 * 36];
    __shared__ __align__(16) u32 sBh[1024];
    __shared__ __align__(16) u32 sBl[1024];

    fill_B(W2, sBh, sBl);
    __syncthreads();

    int lane = threadIdx.x & 31, warp = threadIdx.x >> 5;
    int g_ = lane >> 2, c_ = lane & 3;
    int qid = lane >> 2, qlane = lane & 3;

    unsigned bhb = (unsigned)__cvta_generic_to_shared(sBh) + (unsigned)(g_ * 4 + c_) * 8u;
    unsigned blb = (unsigned)__cvta_generic_to_shared(sBl) + (unsigned)(g_ * 4 + c_) * 8u;

    int tb = (blockIdx.x * 4 + warp) * 32;
    if (tb >= E) return;
    float* myU = &sU[warp][0];

    if (tb + 32 <= E) {
        #pragma unroll
        for (int P = 0; P < 2; P++)
            gather_full(ei, E, tb + 16 * P + 2 * qid,
                        qlane, myU + (16 * P + 2 * qid) * 36 + 4 * qlane);
    } else {
        #pragma unroll
        for (int P = 0; P < 2; P++)
            gather_tail(ei, E, tb + 16 * P + 2 * qid,
                        qlane, myU + (16 * P + 2 * qid) * 36 + 4 * qlane);
    }
    __syncwarp();

    float b20[4], b21[4];
    #pragma unroll
    for (int nt = 0; nt < 4; nt++) {
        b20[nt] = b2[nt * 8 + 2 * c_];
        b21[nt] = b2[nt * 8 + 2 * c_ + 1];
    }

    #pragma unroll
    for (int mt = 0; mt < 2; mt++) {
        float d[4][4];
        mma_tile(myU + mt * 16 * 36, g_, c_, bhb, blb, d);

        ull p01_0 = 0, p23_0 = 0, p01_1 = 0, p23_1 = 0;
        #pragma unroll
        for (int nt = 0; nt < 4; nt++) {
            int col0 = nt * 8 + 2 * c_;
            float m00 = fmaxf(d[nt][0] + b20[nt], 0.f);
            float m01 = fmaxf(d[nt][1] + b21[nt], 0.f);
            float m10 = fmaxf(d[nt][2] + b20[nt], 0.f);
            float m11 = fmaxf(d[nt][3] + b21[nt], 0.f);
            ull qm0 = *(const ull*)(mW + (size_t)col0 * 2);
            ull qv0 = *(const ull*)(vW + (size_t)col0 * 2);
            ull qm1 = *(const ull*)(mW + (size_t)col0 * 2 + 2);
            ull qv1 = *(const ull*)(vW + (size_t)col0 * 2 + 2);
            fma2(p01_0, pack2(m00, m00), qm0); fma2(p23_0, pack2(m00, m00), qv0);
            fma2(p01_0, pack2(m01, m01), qm1); fma2(p23_0, pack2(m01, m01), qv1);
            fma2(p01_1, pack2(m10, m10), qm0); fma2(p23_1, pack2(m10, m10), qv0);
            fma2(p01_1, pack2(m11, m11), qm1); fma2(p23_1, pack2(m11, m11), qv1);
        }
        p01_0 = addp(p01_0, shflx(p01_0, 1)); p01_0 = addp(p01_0, shflx(p01_0, 2));
        p23_0 = addp(p23_0, shflx(p23_0, 1)); p23_0 = addp(p23_0, shflx(p23_0, 2));
        p01_1 = addp(p01_1, shflx(p01_1, 1)); p01_1 = addp(p01_1, shflx(p01_1, 2));
        p23_1 = addp(p23_1, shflx(p23_1, 1)); p23_1 = addp(p23_1, shflx(p23_1, 2));

        if (c_ == 0) {
            int ea = tb + mt * 16 + g_;
            int eb_ = ea + 8;
            if (ea < E) {
                int tg = ei[E + ea];
                float f0, f1, f2, f3;
                unpack2(p01_0, f0, f1); unpack2(p23_0, f2, f3);
                red4(g_sumenc + (size_t)tg * 4, f0, f1, f2, f3);
                redf(&g_cnt[tg], 1.0f);
            }
            if (eb_ < E) {
                int tg = ei[E + eb_];
                float f0, f1, f2, f3;
                unpack2(p01_1, f0, f1); unpack2(p23_1, f2, f3);
                red4(g_sumenc + (size_t)tg * 4, f0, f1, f2, f3);
                redf(&g_cnt[tg], 1.0f);
            }
        }
    }
}

// ---- K4: per-node mid ----
__global__ void k_mid(const float* __restrict__ mb, const float* __restrict__ vb,
                      const float* __restrict__ dW1, const float* __restrict__ db1,
                      const float* __restrict__ eps2,
                      float* __restrict__ out_mu, float* __restrict__ out_lv, int n) {
    __shared__ float sWd[64], sWb[64], sdb1[32], smb[2], svb[2];
    int t = threadIdx.x;
    if (t < 32) {
        sdb1[t] = db1[t];
        sWd[t]      = dW1[t]      - dW1[64 + t];
        sWd[32 + t] = dW1[32 + t] - dW1[96 + t];
        sWb[t]      = dW1[64 + t];
        sWb[32 + t] = dW1[96 + t];
    }
    if (t < 2) { smb[t] = mb[t]; svb[t] = vb[t]; }
    __syncthreads();
    for (int i = blockIdx.x * blockDim.x + t; i < n; i += gridDim.x * blockDim.x) {
        float4 s = ((const float4*)g_sumenc)[i];
        float inv = 1.0f / fmaxf(g_cnt[i], 1.0f);
        float mu0 = s.x * inv + smb[0];
        float mu1 = s.y * inv + smb[1];
        float lv0 = s.z * inv + svb[0];
        float lv1 = s.w * inv + svb[1];
        float2 ep = ((const float2*)eps2)[i];
        float z0 = mu0 + ep.x * expf(0.5f * lv0);
        float z1 = mu1 + ep.y * expf(0.5f * lv1);
        ((float2*)out_mu)[i] = make_float2(mu0, mu1);
        ((float2*)out_lv)[i] = make_float2(lv0, lv1);
        float a[32], b[32];
        #pragma unroll
        for (int o = 0; o < 32; o++) {
            a[o] = sdb1[o] + z0 * sWd[o] + z1 * sWd[32 + o];
            b[o] = z0 * sWb[o] + z1 * sWb[32 + o];
        }
        float4* Ao = (float4*)(g_A + (size_t)i * 32);
        float4* Bo = (float4*)(g_B + (size_t)i * 32);
        #pragma unroll
        for (int q = 0; q < 8; q++) {
            Ao[q] = make_float4(a[4*q], a[4*q+1], a[4*q+2], a[4*q+3]);
            Bo[q] = make_float4(b[4*q], b[4*q+1], b[4*q+2], b[4*q+3]);
        }
    }
}

// ===================== decoder: MMA(tf32 3-term) + W3 epilogue =====================
__global__ void __launch_bounds__(128, 6) k_dec(const int* __restrict__ ei,
                                                const float* __restrict__ W2,
                                                const float* __restrict__ b2,
                                                const float* __restrict__ W3,
                                                const float* __restrict__ b3, int E) {
    __shared__ __align__(16) float sU[4][32 * 36];
    __shared__ __align__(16) u32 sBh[1024];
    __shared__ __align__(16) u32 sBl[1024];

    fill_B(W2, sBh, sBl);
    __syncthreads();

    int lane = threadIdx.x & 31, warp = threadIdx.x >> 5;
    int g_ = lane >> 2, c_ = lane & 3;
    int qid = lane >> 2, qlane = lane & 3;

    unsigned bhb = (unsigned)__cvta_generic_to_shared(sBh) + (unsigned)(g_ * 4 + c_) * 8u;
    unsigned blb = (unsigned)__cvta_generic_to_shared(sBl) + (unsigned)(g_ * 4 + c_) * 8u;

    int tb = (blockIdx.x * 4 + warp) * 32;
    if (tb >= E) return;
    float* myU = &sU[warp][0];

    if (tb + 32 <= E) {
        #pragma unroll
        for (int P = 0; P < 2; P++)
            gather_full(ei, E, tb + 16 * P + 2 * qid,
                        qlane, myU + (16 * P + 2 * qid) * 36 + 4 * qlane);
    } else {
        #pragma unroll
        for (int P = 0; P < 2; P++)
            gather_tail(ei, E, tb + 16 * P + 2 * qid,
                        qlane, myU + (16 * P + 2 * qid) * 36 + 4 * qlane);
    }
    __syncwarp();

    float b20[4], b21[4];
    #pragma unroll
    for (int nt = 0; nt < 4; nt++) {
        b20[nt] = b2[nt * 8 + 2 * c_];
        b21[nt] = b2[nt * 8 + 2 * c_ + 1];
    }
    ull b3a = *(const ull*)(b3);
    ull b3b = *(const ull*)(b3 + 2);

    #pragma unroll
    for (int mt = 0; mt < 2; mt++) {
        float d[4][4];
        mma_tile(myU + mt * 16 * 36, g_, c_, bhb, blb, d);

        ull o01_0 = 0, o23_0 = 0, o01_1 = 0, o23_1 = 0;
        #pragma unroll
        for (int nt = 0; nt < 4; nt++) {
            int col0 = nt * 8 + 2 * c_;
            float m00 = fmaxf(d[nt][0] + b20[nt], 0.f);
            float m01 = fmaxf(d[nt][1] + b21[nt], 0.f);
            float m10 = fmaxf(d[nt][2] + b20[nt], 0.f);
            float m11 = fmaxf(d[nt][3] + b21[nt], 0.f);
            ull w01a = *(const ull*)(W3 + (size_t)col0 * 4);
            ull w23a = *(const ull*)(W3 + (size_t)col0 * 4 + 2);
            ull w01b = *(const ull*)(W3 + (size_t)(col0 + 1) * 4);
            ull w23b = *(const ull*)(W3 + (size_t)(col0 + 1) * 4 + 2);
            fma2(o01_0, pack2(m00, m00), w01a); fma2(o23_0, pack2(m00, m00), w23a);
            fma2(o01_0, pack2(m01, m01), w01b); fma2(o23_0, pack2(m01, m01), w23b);
            fma2(o01_1, pack2(m10, m10), w01a); fma2(o23_1, pack2(m10, m10), w23a);
            fma2(o01_1, pack2(m11, m11), w01b); fma2(o23_1, pack2(m11, m11), w23b);
        }
        o01_0 = addp(o01_0, shflx(o01_0, 1)); o01_0 = addp(o01_0, shflx(o01_0, 2));
        o23_0 = addp(o23_0, shflx(o23_0, 1)); o23_0 = addp(o23_0, shflx(o23_0, 2));
        o01_1 = addp(o01_1, shflx(o01_1, 1)); o01_1 = addp(o01_1, shflx(o01_1, 2));
        o23_1 = addp(o23_1, shflx(o23_1, 1)); o23_1 = addp(o23_1, shflx(o23_1, 2));

        if (c_ == 0) {
            int ea = tb + mt * 16 + g_;
            int eb_ = ea + 8;
            if (ea < E) {
                int tg = ei[E + ea];
                ull r0 = addp(o01_0, b3a), r1 = addp(o23_0, b3b);
                float f0, f1, f2, f3;
                unpack2(r0, f0, f1); unpack2(r1, f2, f3);
                red4(g_sumout + (size_t)tg * 4, f0, f1, f2, f3);
            }
            if (eb_ < E) {
                int tg = ei[E + eb_];
                ull r0 = addp(o01_1, b3a), r1 = addp(o23_1, b3b);
                float f0, f1, f2, f3;
                unpack2(r0, f0, f1); unpack2(r1, f2, f3);
                red4(g_sumout + (size_t)tg * 4, f0, f1, f2, f3);
            }
        }
    }
}

// ---- K6: per-node output mean ----
__global__ void k_out(float* __restrict__ out, int n) {
    for (int i = blockIdx.x * blockDim.x + threadIdx.x; i < n; i += gridDim.x * blockDim.x) {
        float inv = 1.0f / fmaxf(g_cnt[i], 1.0f);
        float4 s = ((const float4*)g_sumout)[i];
        ((float4*)out)[i] = make_float4(s.x * inv, s.y * inv, s.z * inv, s.w * inv);
    }
}

extern "C" void kernel_launch(void* const* d_in, const int* in_sizes, int n_in,
                              void* d_out, int out_size) {
    const float* x     = (const float*)d_in[0];
    const int*   ei    = (const int*)d_in[1];
    const float* eps   = (const float*)d_in[2];
    const float* gamma = (const float*)d_in[3];
    const float* beta  = (const float*)d_in[4];
    const float* eW1   = (const float*)d_in[5];
    const float* eb1   = (const float*)d_in[6];
    const float* eW2   = (const float*)d_in[7];
    const float* eb2   = (const float*)d_in[8];
    const float* mW    = (const float*)d_in[9];
    const float* mb    = (const float*)d_in[10];
    const float* vW    = (const float*)d_in[11];
    const float* vb    = (const float*)d_in[12];
    const float* dW1   = (const float*)d_in[13];
    const float* db1   = (const float*)d_in[14];
    const float* dW2   = (const float*)d_in[15];
    const float* db2   = (const float*)d_in[16];
    const float* dW3   = (const float*)d_in[17];
    const float* db3   = (const float*)d_in[18];

    int n = in_sizes[0] / 4;
    int E = in_sizes[1] / 2;

    float* out    = (float*)d_out;
    float* out_mu = out + (size_t)n * 4;
    float* out_lv = out + (size_t)n * 6;

    int nb = (n + 255) / 256;
    int eb = (E + 127) / 128;

    k_zero<<<256, 256>>>(n);
    k_stats<<<256, 256>>>((const float4*)x, n);
    k_pre<<<nb, 256>>>((const float4*)x, gamma, beta, eW1, eb1, n, 1.0f / (float)n);
    k_enc<<<eb, 128>>>(ei, eW2, eb2, mW, vW, E);
    k_mid<<<nb, 256>>>(mb, vb, dW1, db1, eps, out_mu, out_lv, n);
    k_dec<<<eb, 128>>>(ei, dW2, db2, dW3, db3, E);
    k_out<<<nb, 256>>>(out, n);
}

// round 10
// speedup vs baseline: 2.4495x; 1.3776x over previous
#include <cuda_runtime.h>
#include <math.h>

#define N_MAX 100000
typedef unsigned long long ull;
typedef unsigned int u32;

// ---- scratch ----
__device__ __align__(16) float g_A[N_MAX * 32];
__device__ __align__(16) float g_B[N_MAX * 32];
__device__ __align__(16) float g_sumenc[N_MAX * 4];
__device__ __align__(16) float g_cnt[N_MAX];
__device__ __align__(16) float g_sumout[N_MAX * 4];
__device__ __align__(16) float g_stats[8];

// ---- helpers ----
__device__ __forceinline__ ull pack2(float x, float y) {
    ull r; asm("mov.b64 %0, {%1,%2};" : "=l"(r) : "f"(x), "f"(y)); return r;
}
__device__ __forceinline__ void unpack2(ull v, float& x, float& y) {
    asm("mov.b64 {%0,%1}, %2;" : "=f"(x), "=f"(y) : "l"(v));
}
__device__ __forceinline__ void fma2(ull& d, ull a, ull b) {
    asm("fma.rn.f32x2 %0, %1, %2, %3;" : "=l"(d) : "l"(a), "l"(b), "l"(d));
}
__device__ __forceinline__ ull addp(ull a, ull b) {
    ull r; asm("add.rn.f32x2 %0, %1, %2;" : "=l"(r) : "l"(a), "l"(b)); return r;
}
__device__ __forceinline__ void red4(float* p, float a, float b, float c, float d) {
    asm volatile("red.global.add.v4.f32 [%0], {%1,%2,%3,%4};"
                 :: "l"(p), "f"(a), "f"(b), "f"(c), "f"(d) : "memory");
}
__device__ __forceinline__ void redf(float* p, float v) {
    asm volatile("red.global.add.f32 [%0], %1;" :: "l"(p), "f"(v) : "memory");
}
__device__ __forceinline__ ull shflx(ull v, int m) {
    return __shfl_xor_sync(0xffffffffu, v, m);
}
// pack two f32 -> bf16x2 (lo=x, hi=y)
__device__ __forceinline__ u32 bfpack(float y, float x) {
    u32 r; asm("cvt.rn.bf16x2.f32 %0, %1, %2;" : "=r"(r) : "f"(y), "f"(x)); return r;
}
// split (x,y) into bf16x2 high part h and bf16x2 residual l
__device__ __forceinline__ void bsplit(float x, float y, u32& h, u32& l) {
    h = bfpack(y, x);
    float xr = x - __uint_as_float(h << 16);
    float yr = y - __uint_as_float(h & 0xFFFF0000u);
    l = bfpack(yr, xr);
}
__device__ __forceinline__ void mma16(float* d, const u32* a, u32 b0, u32 b1) {
    asm volatile("mma.sync.aligned.m16n8k16.row.col.f32.bf16.bf16.f32 "
                 "{%0,%1,%2,%3},{%4,%5,%6,%7},{%8,%9},{%0,%1,%2,%3};"
                 : "+f"(d[0]), "+f"(d[1]), "+f"(d[2]), "+f"(d[3])
                 : "r"(a[0]), "r"(a[1]), "r"(a[2]), "r"(a[3]), "r"(b0), "r"(b1));
}
__device__ __forceinline__ void lds128(unsigned addr, u32& a, u32& b, u32& c, u32& d) {
    asm volatile("ld.shared.v4.u32 {%0,%1,%2,%3}, [%4];"
                 : "=r"(a), "=r"(b), "=r"(c), "=r"(d) : "r"(addr));
}

// ---- K0: zero accumulators ----
__global__ void k_zero(int n) {
    int i = blockIdx.x * blockDim.x + threadIdx.x;
    int stride = gridDim.x * blockDim.x;
    float4 z = make_float4(0.f, 0.f, 0.f, 0.f);
    float4* a = (float4*)g_sumenc; int na = n;
    for (int t = i; t < na; t += stride) a[t] = z;
    float4* b = (float4*)g_sumout; int nb = n;
    for (int t = i; t < nb; t += stride) b[t] = z;
    float4* c = (float4*)g_cnt;    int nc = n >> 2;
    for (int t = i; t < nc; t += stride) c[t] = z;
    if (i < 8) g_stats[i] = 0.f;
}

// ---- K1: batchnorm statistics ----
__global__ void k_stats(const float4* __restrict__ x, int n) {
    float sx = 0, sy = 0, sz = 0, sw = 0, qx = 0, qy = 0, qz = 0, qw = 0;
    for (int i = blockIdx.x * blockDim.x + threadIdx.x; i < n; i += gridDim.x * blockDim.x) {
        float4 v = x[i];
        sx += v.x; sy += v.y; sz += v.z; sw += v.w;
        qx += v.x * v.x; qy += v.y * v.y; qz += v.z * v.z; qw += v.w * v.w;
    }
    #pragma unroll
    for (int off = 16; off; off >>= 1) {
        sx += __shfl_down_sync(0xffffffffu, sx, off);
        sy += __shfl_down_sync(0xffffffffu, sy, off);
        sz += __shfl_down_sync(0xffffffffu, sz, off);
        sw += __shfl_down_sync(0xffffffffu, sw, off);
        qx += __shfl_down_sync(0xffffffffu, qx, off);
        qy += __shfl_down_sync(0xffffffffu, qy, off);
        qz += __shfl_down_sync(0xffffffffu, qz, off);
        qw += __shfl_down_sync(0xffffffffu, qw, off);
    }
    if ((threadIdx.x & 31) == 0) {
        atomicAdd(&g_stats[0], sx); atomicAdd(&g_stats[1], sy);
        atomicAdd(&g_stats[2], sz); atomicAdd(&g_stats[3], sw);
        atomicAdd(&g_stats[4], qx); atomicAdd(&g_stats[5], qy);
        atomicAdd(&g_stats[6], qz); atomicAdd(&g_stats[7], qw);
    }
}

// ---- K2: BN + encoder layer-1 split ----
__global__ void k_pre(const float4* __restrict__ x,
                      const float* __restrict__ gamma, const float* __restrict__ beta,
                      const float* __restrict__ eW1, const float* __restrict__ eb1,
                      int n, float invN) {
    __shared__ float sWd[128], sWb[128], sb1[32], sScale[4], sShift[4];
    int t = threadIdx.x;
    if (t < 128) {
        int c = t >> 5, o = t & 31;
        float wa = eW1[c * 32 + o], wb = eW1[(4 + c) * 32 + o];
        sWd[t] = wa - wb; sWb[t] = wb;
    }
    if (t < 32) sb1[t] = eb1[t];
    if (t < 4) {
        float m = g_stats[t] * invN;
        float v = g_stats[4 + t] * invN - m * m;
        float s = rsqrtf(v + 1e-5f) * gamma[t];
        sScale[t] = s; sShift[t] = beta[t] - m * s;
    }
    __syncthreads();
    for (int i = blockIdx.x * blockDim.x + t; i < n; i += gridDim.x * blockDim.x) {
        float4 xv = x[i];
        float xn[4];
        xn[0] = xv.x * sScale[0] + sShift[0];
        xn[1] = xv.y * sScale[1] + sShift[1];
        xn[2] = xv.z * sScale[2] + sShift[2];
        xn[3] = xv.w * sScale[3] + sShift[3];
        float a[32], b[32];
        #pragma unroll
        for (int o = 0; o < 32; o++) {
            float av = sb1[o], bv = 0.f;
            #pragma unroll
            for (int c = 0; c < 4; c++) {
                av += xn[c] * sWd[c * 32 + o];
                bv += xn[c] * sWb[c * 32 + o];
            }
            a[o] = av; b[o] = bv;
        }
        float4* Ao = (float4*)(g_A + (size_t)i * 32);
        float4* Bo = (float4*)(g_B + (size_t)i * 32);
        #pragma unroll
        for (int q = 0; q < 8; q++) {
            Ao[q] = make_float4(a[4*q], a[4*q+1], a[4*q+2], a[4*q+3]);
            Bo[q] = make_float4(b[4*q], b[4*q+1], b[4*q+2], b[4*q+3]);
        }
    }
}

// ---- fill B tile: slot(kt,nt,lane) = {bh0, bh1, bl0, bl1} (bf16x2 pairs) ----
__device__ __forceinline__ void fill_B16(const float* __restrict__ W, uint4* sB) {
    for (int idx = threadIdx.x; idx < 256; idx += 128) {
        int kt = idx >> 7, nt = (idx >> 5) & 3, l = idx & 31;
        int g = l >> 2, c = l & 3;
        int col = nt * 8 + g;
        int r0 = kt * 16 + 2 * c;
        float w0 = W[(size_t)r0 * 32 + col];
        float w1 = W[(size_t)(r0 + 1) * 32 + col];
        float w2 = W[(size_t)(r0 + 8) * 32 + col];
        float w3 = W[(size_t)(r0 + 9) * 32 + col];
        u32 h0, l0, h1, l1;
        bsplit(w0, w1, h0, l0);
        bsplit(w2, w3, h1, l1);
        sB[idx] = make_uint4(h0, h1, l0, l1);
    }
}

// ---- 3-term bf16 MMA of one 16x32 u-tile (row stride 40) ----
__device__ __forceinline__ void mma_tile16(const float* ub, int g_, int c_,
                                           unsigned bb, float d[4][4]) {
    #pragma unroll
    for (int nt = 0; nt < 4; nt++)
        #pragma unroll
        for (int j = 0; j < 4; j++) d[nt][j] = 0.f;
    #pragma unroll
    for (int kt = 0; kt < 2; kt++) {
        const float* p0 = ub + g_ * 40 + kt * 16 + 2 * c_;
        const float* p1 = ub + (g_ + 8) * 40 + kt * 16 + 2 * c_;
        float2 f0 = *(const float2*)p0;
        float2 f1 = *(const float2*)p1;
        float2 f2 = *(const float2*)(p0 + 8);
        float2 f3 = *(const float2*)(p1 + 8);
        u32 ah[4], al[4];
        bsplit(f0.x, f0.y, ah[0], al[0]);
        bsplit(f1.x, f1.y, ah[1], al[1]);
        bsplit(f2.x, f2.y, ah[2], al[2]);
        bsplit(f3.x, f3.y, ah[3], al[3]);
        #pragma unroll
        for (int nt = 0; nt < 4; nt++) {
            u32 b0, b1, c0, c1;
            lds128(bb + (unsigned)(kt * 4 + nt) * 512u, b0, b1, c0, c1);
            mma16(d[nt], ah, b0, b1);
            mma16(d[nt], al, b0, b1);
            mma16(d[nt], ah, c0, c1);
        }
    }
}

// ---- octet gather: 8 lanes per edge, one full 128B row per LDG line ----
__device__ __forceinline__ void gather32(int s_all, int t_all, int oct, int sub, float* myU) {
    #pragma unroll
    for (int p = 0; p < 8; p++) {
        int e_sub = 4 * p + oct;
        int s = __shfl_sync(0xffffffffu, s_all, e_sub);
        int t = __shfl_sync(0xffffffffu, t_all, e_sub);
        float4 a = __ldg((const float4*)(g_A + (size_t)t * 32) + sub);
        float4 b = __ldg((const float4*)(g_B + (size_t)s * 32) + sub);
        *(float4*)(myU + e_sub * 40 + sub * 4) = make_float4(
            fmaxf(a.x + b.x, 0.f), fmaxf(a.y + b.y, 0.f),
            fmaxf(a.z + b.z, 0.f), fmaxf(a.w + b.w, 0.f));
    }
}

// ===================== encoder =====================
__global__ void __launch_bounds__(128, 6) k_enc(const int* __restrict__ ei,
                                                const float* __restrict__ W2,
                                                const float* __restrict__ b2,
                                                const float* __restrict__ mW,
                                                const float* __restrict__ vW, int E) {
    __shared__ __align__(16) float sU[4][32 * 40];
    __shared__ __align__(16) uint4 sB[256];

    fill_B16(W2, sB);
    __syncthreads();

    int lane = threadIdx.x & 31, warp = threadIdx.x >> 5;
    int g_ = lane >> 2, c_ = lane & 3;
    int oct = lane >> 3, sub = lane & 7;
    unsigned bb = (unsigned)__cvta_generic_to_shared(sB) + (unsigned)lane * 16u;

    int tb = (blockIdx.x * 4 + warp) * 32;
    if (tb >= E) return;
    int idx = tb + lane;
    int s_all = 0, t_all = 0;
    if (idx < E) { s_all = ei[idx]; t_all = ei[E + idx]; }

    float* myU = &sU[warp][0];
    gather32(s_all, t_all, oct, sub, myU);
    __syncwarp();

    float b20[4], b21[4];
    #pragma unroll
    for (int nt = 0; nt < 4; nt++) {
        b20[nt] = b2[nt * 8 + 2 * c_];
        b21[nt] = b2[nt * 8 + 2 * c_ + 1];
    }

    #pragma unroll
    for (int mt = 0; mt < 2; mt++) {
        float d[4][4];
        mma_tile16(myU + mt * 16 * 40, g_, c_, bb, d);

        ull p01_0 = 0, p23_0 = 0, p01_1 = 0, p23_1 = 0;
        #pragma unroll
        for (int nt = 0; nt < 4; nt++) {
            int col0 = nt * 8 + 2 * c_;
            float m00 = fmaxf(d[nt][0] + b20[nt], 0.f);
            float m01 = fmaxf(d[nt][1] + b21[nt], 0.f);
            float m10 = fmaxf(d[nt][2] + b20[nt], 0.f);
            float m11 = fmaxf(d[nt][3] + b21[nt], 0.f);
            ull qm0 = *(const ull*)(mW + (size_t)col0 * 2);
            ull qv0 = *(const ull*)(vW + (size_t)col0 * 2);
            ull qm1 = *(const ull*)(mW + (size_t)col0 * 2 + 2);
            ull qv1 = *(const ull*)(vW + (size_t)col0 * 2 + 2);
            fma2(p01_0, pack2(m00, m00), qm0); fma2(p23_0, pack2(m00, m00), qv0);
            fma2(p01_0, pack2(m01, m01), qm1); fma2(p23_0, pack2(m01, m01), qv1);
            fma2(p01_1, pack2(m10, m10), qm0); fma2(p23_1, pack2(m10, m10), qv0);
            fma2(p01_1, pack2(m11, m11), qm1); fma2(p23_1, pack2(m11, m11), qv1);
        }
        p01_0 = addp(p01_0, shflx(p01_0, 1)); p01_0 = addp(p01_0, shflx(p01_0, 2));
        p23_0 = addp(p23_0, shflx(p23_0, 1)); p23_0 = addp(p23_0, shflx(p23_0, 2));
        p01_1 = addp(p01_1, shflx(p01_1, 1)); p01_1 = addp(p01_1, shflx(p01_1, 2));
        p23_1 = addp(p23_1, shflx(p23_1, 1)); p23_1 = addp(p23_1, shflx(p23_1, 2));

        int tga = __shfl_sync(0xffffffffu, t_all, mt * 16 + g_);
        int tgb = __shfl_sync(0xffffffffu, t_all, mt * 16 + 8 + g_);
        if (c_ == 0) {
            int ea = tb + mt * 16 + g_;
            int eb_ = ea + 8;
            if (ea < E) {
                float f0, f1, f2, f3;
                unpack2(p01_0, f0, f1); unpack2(p23_0, f2, f3);
                red4(g_sumenc + (size_t)tga * 4, f0, f1, f2, f3);
                redf(&g_cnt[tga], 1.0f);
            }
            if (eb_ < E) {
                float f0, f1, f2, f3;
                unpack2(p01_1, f0, f1); unpack2(p23_1, f2, f3);
                red4(g_sumenc + (size_t)tgb * 4, f0, f1, f2, f3);
                redf(&g_cnt[tgb], 1.0f);
            }
        }
    }
}

// ---- K4: per-node mid ----
__global__ void k_mid(const float* __restrict__ mb, const float* __restrict__ vb,
                      const float* __restrict__ dW1, const float* __restrict__ db1,
                      const float* __restrict__ eps2,
                      float* __restrict__ out_mu, float* __restrict__ out_lv, int n) {
    __shared__ float sWd[64], sWb[64], sdb1[32], smb[2], svb[2];
    int t = threadIdx.x;
    if (t < 32) {
        sdb1[t] = db1[t];
        sWd[t]      = dW1[t]      - dW1[64 + t];
        sWd[32 + t] = dW1[32 + t] - dW1[96 + t];
        sWb[t]      = dW1[64 + t];
        sWb[32 + t] = dW1[96 + t];
    }
    if (t < 2) { smb[t] = mb[t]; svb[t] = vb[t]; }
    __syncthreads();
    for (int i = blockIdx.x * blockDim.x + t; i < n; i += gridDim.x * blockDim.x) {
        float4 s = ((const float4*)g_sumenc)[i];
        float inv = 1.0f / fmaxf(g_cnt[i], 1.0f);
        float mu0 = s.x * inv + smb[0];
        float mu1 = s.y * inv + smb[1];
        float lv0 = s.z * inv + svb[0];
        float lv1 = s.w * inv + svb[1];
        float2 ep = ((const float2*)eps2)[i];
        float z0 = mu0 + ep.x * expf(0.5f * lv0);
        float z1 = mu1 + ep.y * expf(0.5f * lv1);
        ((float2*)out_mu)[i] = make_float2(mu0, mu1);
        ((float2*)out_lv)[i] = make_float2(lv0, lv1);
        float a[32], b[32];
        #pragma unroll
        for (int o = 0; o < 32; o++) {
            a[o] = sdb1[o] + z0 * sWd[o] + z1 * sWd[32 + o];
            b[o] = z0 * sWb[o] + z1 * sWb[32 + o];
        }
        float4* Ao = (float4*)(g_A + (size_t)i * 32);
        float4* Bo = (float4*)(g_B + (size_t)i * 32);
        #pragma unroll
        for (int q = 0; q < 8; q++) {
            Ao[q] = make_float4(a[4*q], a[4*q+1], a[4*q+2], a[4*q+3]);
            Bo[q] = make_float4(b[4*q], b[4*q+1], b[4*q+2], b[4*q+3]);
        }
    }
}

// ===================== decoder =====================
__global__ void __launch_bounds__(128, 6) k_dec(const int* __restrict__ ei,
                                                const float* __restrict__ W2,
                                                const float* __restrict__ b2,
                                                const float* __restrict__ W3,
                                                const float* __restrict__ b3, int E) {
    __shared__ __align__(16) float sU[4][32 * 40];
    __shared__ __align__(16) uint4 sB[256];

    fill_B16(W2, sB);
    __syncthreads();

    int lane = threadIdx.x & 31, warp = threadIdx.x >> 5;
    int g_ = lane >> 2, c_ = lane & 3;
    int oct = lane >> 3, sub = lane & 7;
    unsigned bb = (unsigned)__cvta_generic_to_shared(sB) + (unsigned)lane * 16u;

    int tb = (blockIdx.x * 4 + warp) * 32;
    if (tb >= E) return;
    int idx = tb + lane;
    int s_all = 0, t_all = 0;
    if (idx < E) { s_all = ei[idx]; t_all = ei[E + idx]; }

    float* myU = &sU[warp][0];
    gather32(s_all, t_all, oct, sub, myU);
    __syncwarp();

    float b20[4], b21[4];
    #pragma unroll
    for (int nt = 0; nt < 4; nt++) {
        b20[nt] = b2[nt * 8 + 2 * c_];
        b21[nt] = b2[nt * 8 + 2 * c_ + 1];
    }
    ull b3a = *(const ull*)(b3);
    ull b3b = *(const ull*)(b3 + 2);

    #pragma unroll
    for (int mt = 0; mt < 2; mt++) {
        float d[4][4];
        mma_tile16(myU + mt * 16 * 40, g_, c_, bb, d);

        ull o01_0 = 0, o23_0 = 0, o01_1 = 0, o23_1 = 0;
        #pragma unroll
        for (int nt = 0; nt < 4; nt++) {
            int col0 = nt * 8 + 2 * c_;
            float m00 = fmaxf(d[nt][0] + b20[nt], 0.f);
            float m01 = fmaxf(d[nt][1] + b21[nt], 0.f);
            float m10 = fmaxf(d[nt][2] + b20[nt], 0.f);
            float m11 = fmaxf(d[nt][3] + b21[nt], 0.f);
            ull w01a = *(const ull*)(W3 + (size_t)col0 * 4);
            ull w23a = *(const ull*)(W3 + (size_t)col0 * 4 + 2);
            ull w01b = *(const ull*)(W3 + (size_t)(col0 + 1) * 4);
            ull w23b = *(const ull*)(W3 + (size_t)(col0 + 1) * 4 + 2);
            fma2(o01_0, pack2(m00, m00), w01a); fma2(o23_0, pack2(m00, m00), w23a);
            fma2(o01_0, pack2(m01, m01), w01b); fma2(o23_0, pack2(m01, m01), w23b);
            fma2(o01_1, pack2(m10, m10), w01a); fma2(o23_1, pack2(m10, m10), w23a);
            fma2(o01_1, pack2(m11, m11), w01b); fma2(o23_1, pack2(m11, m11), w23b);
        }
        o01_0 = addp(o01_0, shflx(o01_0, 1)); o01_0 = addp(o01_0, shflx(o01_0, 2));
        o23_0 = addp(o23_0, shflx(o23_0, 1)); o23_0 = addp(o23_0, shflx(o23_0, 2));
        o01_1 = addp(o01_1, shflx(o01_1, 1)); o01_1 = addp(o01_1, shflx(o01_1, 2));
        o23_1 = addp(o23_1, shflx(o23_1, 1)); o23_1 = addp(o23_1, shflx(o23_1, 2));

        int tga = __shfl_sync(0xffffffffu, t_all, mt * 16 + g_);
        int tgb = __shfl_sync(0xffffffffu, t_all, mt * 16 + 8 + g_);
        if (c_ == 0) {
            int ea = tb + mt * 16 + g_;
            int eb_ = ea + 8;
            if (ea < E) {
                ull r0 = addp(o01_0, b3a), r1 = addp(o23_0, b3b);
                float f0, f1, f2, f3;
                unpack2(r0, f0, f1); unpack2(r1, f2, f3);
                red4(g_sumout + (size_t)tga * 4, f0, f1, f2, f3);
            }
            if (eb_ < E) {
                ull r0 = addp(o01_1, b3a), r1 = addp(o23_1, b3b);
                float f0, f1, f2, f3;
                unpack2(r0, f0, f1); unpack2(r1, f2, f3);
                red4(g_sumout + (size_t)tgb * 4, f0, f1, f2, f3);
            }
        }
    }
}

// ---- K6: per-node output mean ----
__global__ void k_out(float* __restrict__ out, int n) {
    for (int i = blockIdx.x * blockDim.x + threadIdx.x; i < n; i += gridDim.x * blockDim.x) {
        float inv = 1.0f / fmaxf(g_cnt[i], 1.0f);
        float4 s = ((const float4*)g_sumout)[i];
        ((float4*)out)[i] = make_float4(s.x * inv, s.y * inv, s.z * inv, s.w * inv);
    }
}

extern "C" void kernel_launch(void* const* d_in, const int* in_sizes, int n_in,
                              void* d_out, int out_size) {
    const float* x     = (const float*)d_in[0];
    const int*   ei    = (const int*)d_in[1];
    const float* eps   = (const float*)d_in[2];
    const float* gamma = (const float*)d_in[3];
    const float* beta  = (const float*)d_in[4];
    const float* eW1   = (const float*)d_in[5];
    const float* eb1   = (const float*)d_in[6];
    const float* eW2   = (const float*)d_in[7];
    const float* eb2   = (const float*)d_in[8];
    const float* mW    = (const float*)d_in[9];
    const float* mb    = (const float*)d_in[10];
    const float* vW    = (const float*)d_in[11];
    const float* vb    = (const float*)d_in[12];
    const float* dW1   = (const float*)d_in[13];
    const float* db1   = (const float*)d_in[14];
    const float* dW2   = (const float*)d_in[15];
    const float* db2   = (const float*)d_in[16];
    const float* dW3   = (const float*)d_in[17];
    const float* db3   = (const float*)d_in[18];

    int n = in_sizes[0] / 4;
    int E = in_sizes[1] / 2;

    float* out    = (float*)d_out;
    float* out_mu = out + (size_t)n * 4;
    float* out_lv = out + (size_t)n * 6;

    int nb = (n + 255) / 256;
    int eb = (E + 127) / 128;

    k_zero<<<256, 256>>>(n);
    k_stats<<<256, 256>>>((const float4*)x, n);
    k_pre<<<nb, 256>>>((const float4*)x, gamma, beta, eW1, eb1, n, 1.0f / (float)n);
    k_enc<<<eb, 128>>>(ei, eW2, eb2, mW, vW, E);
    k_mid<<<nb, 256>>>(mb, vb, dW1, db1, eps, out_mu, out_lv, n);
    k_dec<<<eb, 128>>>(ei, dW2, db2, dW3, db3, E);
    k_out<<<nb, 256>>>(out, n);
}

// round 11
// speedup vs baseline: 2.5238x; 1.0303x over previous
#include <cuda_runtime.h>
#include <math.h>

#define N_MAX 100000
typedef unsigned long long ull;
typedef unsigned int u32;

// ---- scratch ----
__device__ __align__(16) float g_A[N_MAX * 32];
__device__ __align__(16) float g_B[N_MAX * 32];
__device__ __align__(16) float g_sumenc[N_MAX * 4];
__device__ __align__(16) float g_cnt[N_MAX];
__device__ __align__(16) float g_sumout[N_MAX * 4];
__device__ __align__(16) float g_stats[8];

// ---- helpers ----
__device__ __forceinline__ void red4(float* p, float a, float b, float c, float d) {
    asm volatile("red.global.add.v4.f32 [%0], {%1,%2,%3,%4};"
                 :: "l"(p), "f"(a), "f"(b), "f"(c), "f"(d) : "memory");
}
__device__ __forceinline__ void redf(float* p, float v) {
    asm volatile("red.global.add.f32 [%0], %1;" :: "l"(p), "f"(v) : "memory");
}
// pack two f32 -> bf16x2 (lo=x, hi=y)
__device__ __forceinline__ u32 bfpack(float y, float x) {
    u32 r; asm("cvt.rn.bf16x2.f32 %0, %1, %2;" : "=r"(r) : "f"(y), "f"(x)); return r;
}
// split (x,y) into bf16x2 high h and residual l
__device__ __forceinline__ void bsplit(float x, float y, u32& h, u32& l) {
    h = bfpack(y, x);
    float xr = x - __uint_as_float(h << 16);
    float yr = y - __uint_as_float(h & 0xFFFF0000u);
    l = bfpack(yr, xr);
}
__device__ __forceinline__ void mma16(float* d, const u32* a, u32 b0, u32 b1) {
    asm volatile("mma.sync.aligned.m16n8k16.row.col.f32.bf16.bf16.f32 "
                 "{%0,%1,%2,%3},{%4,%5,%6,%7},{%8,%9},{%0,%1,%2,%3};"
                 : "+f"(d[0]), "+f"(d[1]), "+f"(d[2]), "+f"(d[3])
                 : "r"(a[0]), "r"(a[1]), "r"(a[2]), "r"(a[3]), "r"(b0), "r"(b1));
}
__device__ __forceinline__ void lds128(unsigned addr, u32& a, u32& b, u32& c, u32& d) {
    asm volatile("ld.shared.v4.u32 {%0,%1,%2,%3}, [%4];"
                 : "=r"(a), "=r"(b), "=r"(c), "=r"(d) : "r"(addr));
}

// ---- K0: zero accumulators ----
__global__ void k_zero(int n) {
    int i = blockIdx.x * blockDim.x + threadIdx.x;
    int stride = gridDim.x * blockDim.x;
    float4 z = make_float4(0.f, 0.f, 0.f, 0.f);
    float4* a = (float4*)g_sumenc; int na = n;
    for (int t = i; t < na; t += stride) a[t] = z;
    float4* b = (float4*)g_sumout; int nb = n;
    for (int t = i; t < nb; t += stride) b[t] = z;
    float4* c = (float4*)g_cnt;    int nc = n >> 2;
    for (int t = i; t < nc; t += stride) c[t] = z;
    if (i < 8) g_stats[i] = 0.f;
}

// ---- K1: batchnorm statistics ----
__global__ void k_stats(const float4* __restrict__ x, int n) {
    float sx = 0, sy = 0, sz = 0, sw = 0, qx = 0, qy = 0, qz = 0, qw = 0;
    for (int i = blockIdx.x * blockDim.x + threadIdx.x; i < n; i += gridDim.x * blockDim.x) {
        float4 v = x[i];
        sx += v.x; sy += v.y; sz += v.z; sw += v.w;
        qx += v.x * v.x; qy += v.y * v.y; qz += v.z * v.z; qw += v.w * v.w;
    }
    #pragma unroll
    for (int off = 16; off; off >>= 1) {
        sx += __shfl_down_sync(0xffffffffu, sx, off);
        sy += __shfl_down_sync(0xffffffffu, sy, off);
        sz += __shfl_down_sync(0xffffffffu, sz, off);
        sw += __shfl_down_sync(0xffffffffu, sw, off);
        qx += __shfl_down_sync(0xffffffffu, qx, off);
        qy += __shfl_down_sync(0xffffffffu, qy, off);
        qz += __shfl_down_sync(0xffffffffu, qz, off);
        qw += __shfl_down_sync(0xffffffffu, qw, off);
    }
    if ((threadIdx.x & 31) == 0) {
        atomicAdd(&g_stats[0], sx); atomicAdd(&g_stats[1], sy);
        atomicAdd(&g_stats[2], sz); atomicAdd(&g_stats[3], sw);
        atomicAdd(&g_stats[4], qx); atomicAdd(&g_stats[5], qy);
        atomicAdd(&g_stats[6], qz); atomicAdd(&g_stats[7], qw);
    }
}

// ---- K2: BN + encoder layer-1 split ----
__global__ void k_pre(const float4* __restrict__ x,
                      const float* __restrict__ gamma, const float* __restrict__ beta,
                      const float* __restrict__ eW1, const float* __restrict__ eb1,
                      int n, float invN) {
    __shared__ float sWd[128], sWb[128], sb1[32], sScale[4], sShift[4];
    int t = threadIdx.x;
    if (t < 128) {
        int c = t >> 5, o = t & 31;
        float wa = eW1[c * 32 + o], wb = eW1[(4 + c) * 32 + o];
        sWd[t] = wa - wb; sWb[t] = wb;
    }
    if (t < 32) sb1[t] = eb1[t];
    if (t < 4) {
        float m = g_stats[t] * invN;
        float v = g_stats[4 + t] * invN - m * m;
        float s = rsqrtf(v + 1e-5f) * gamma[t];
        sScale[t] = s; sShift[t] = beta[t] - m * s;
    }
    __syncthreads();
    for (int i = blockIdx.x * blockDim.x + t; i < n; i += gridDim.x * blockDim.x) {
        float4 xv = x[i];
        float xn[4];
        xn[0] = xv.x * sScale[0] + sShift[0];
        xn[1] = xv.y * sScale[1] + sShift[1];
        xn[2] = xv.z * sScale[2] + sShift[2];
        xn[3] = xv.w * sScale[3] + sShift[3];
        float a[32], b[32];
        #pragma unroll
        for (int o = 0; o < 32; o++) {
            float av = sb1[o], bv = 0.f;
            #pragma unroll
            for (int c = 0; c < 4; c++) {
                av += xn[c] * sWd[c * 32 + o];
                bv += xn[c] * sWb[c * 32 + o];
            }
            a[o] = av; b[o] = bv;
        }
        float4* Ao = (float4*)(g_A + (size_t)i * 32);
        float4* Bo = (float4*)(g_B + (size_t)i * 32);
        #pragma unroll
        for (int q = 0; q < 8; q++) {
            Ao[q] = make_float4(a[4*q], a[4*q+1], a[4*q+2], a[4*q+3]);
            Bo[q] = make_float4(b[4*q], b[4*q+1], b[4*q+2], b[4*q+3]);
        }
    }
}

// ---- fill B tile: slot(kt,nt,lane) = {bh0, bh1, bl0, bl1} ----
__device__ __forceinline__ void fill_B16(const float* __restrict__ W, uint4* sB) {
    for (int idx = threadIdx.x; idx < 256; idx += 128) {
        int kt = idx >> 7, nt = (idx >> 5) & 3, l = idx & 31;
        int g = l >> 2, c = l & 3;
        int col = nt * 8 + g;
        int r0 = kt * 16 + 2 * c;
        float w0 = W[(size_t)r0 * 32 + col];
        float w1 = W[(size_t)(r0 + 1) * 32 + col];
        float w2 = W[(size_t)(r0 + 8) * 32 + col];
        float w3 = W[(size_t)(r0 + 9) * 32 + col];
        u32 h0, l0, h1, l1;
        bsplit(w0, w1, h0, l0);
        bsplit(w2, w3, h1, l1);
        sB[idx] = make_uint4(h0, h1, l0, l1);
    }
}

// ---- 3-term bf16 MMA of one 16x32 u-tile (row stride 40) ----
__device__ __forceinline__ void mma_tile16(const float* ub, int g_, int c_,
                                           unsigned bb, float d[4][4]) {
    #pragma unroll
    for (int nt = 0; nt < 4; nt++)
        #pragma unroll
        for (int j = 0; j < 4; j++) d[nt][j] = 0.f;
    #pragma unroll
    for (int kt = 0; kt < 2; kt++) {
        const float* p0 = ub + g_ * 40 + kt * 16 + 2 * c_;
        const float* p1 = ub + (g_ + 8) * 40 + kt * 16 + 2 * c_;
        float2 f0 = *(const float2*)p0;
        float2 f1 = *(const float2*)p1;
        float2 f2 = *(const float2*)(p0 + 8);
        float2 f3 = *(const float2*)(p1 + 8);
        u32 ah[4], al[4];
        bsplit(f0.x, f0.y, ah[0], al[0]);
        bsplit(f1.x, f1.y, ah[1], al[1]);
        bsplit(f2.x, f2.y, ah[2], al[2]);
        bsplit(f3.x, f3.y, ah[3], al[3]);
        #pragma unroll
        for (int nt = 0; nt < 4; nt++) {
            u32 b0, b1, c0, c1;
            lds128(bb + (unsigned)(kt * 4 + nt) * 512u, b0, b1, c0, c1);
            mma16(d[nt], ah, b0, b1);
            mma16(d[nt], al, b0, b1);
            mma16(d[nt], ah, c0, c1);
        }
    }
}

// ---- projection MMA: msg(32cols as k) @ P(32x4); d frags -> d2 frags ----
// ph/pl: per kt2: {rows kt2*16+2c,+1 col g} and {+8,+9 col g}
__device__ __forceinline__ void proj_mma(const float d[4][4],
                                         const float b20[4], const float b21[4],
                                         const u32 ph[2][2], const u32 pl[2][2],
                                         float d2[4]) {
    d2[0] = d2[1] = d2[2] = d2[3] = 0.f;
    #pragma unroll
    for (int kt2 = 0; kt2 < 2; kt2++) {
        int n0 = 2 * kt2, n1 = n0 + 1;
        float m00 = fmaxf(d[n0][0] + b20[n0], 0.f);
        float m01 = fmaxf(d[n0][1] + b21[n0], 0.f);
        float m02 = fmaxf(d[n0][2] + b20[n0], 0.f);
        float m03 = fmaxf(d[n0][3] + b21[n0], 0.f);
        float m10 = fmaxf(d[n1][0] + b20[n1], 0.f);
        float m11 = fmaxf(d[n1][1] + b21[n1], 0.f);
        float m12 = fmaxf(d[n1][2] + b20[n1], 0.f);
        float m13 = fmaxf(d[n1][3] + b21[n1], 0.f);
        u32 ah[4], al[4];
        bsplit(m00, m01, ah[0], al[0]);   // (row g,   k 2c,2c+1)
        bsplit(m02, m03, ah[1], al[1]);   // (row g+8, k 2c,2c+1)
        bsplit(m10, m11, ah[2], al[2]);   // (row g,   k 8+2c)
        bsplit(m12, m13, ah[3], al[3]);   // (row g+8, k 8+2c)
        mma16(d2, ah, ph[kt2][0], ph[kt2][1]);
        mma16(d2, al, ph[kt2][0], ph[kt2][1]);
        mma16(d2, ah, pl[kt2][0], pl[kt2][1]);
    }
}

// ---- octet gather: 8 lanes per edge, one full 128B row per LDG line ----
__device__ __forceinline__ void gather32(int s_all, int t_all, int oct, int sub, float* myU) {
    #pragma unroll
    for (int p = 0; p < 8; p++) {
        int e_sub = 4 * p + oct;
        int s = __shfl_sync(0xffffffffu, s_all, e_sub);
        int t = __shfl_sync(0xffffffffu, t_all, e_sub);
        float4 a = __ldg((const float4*)(g_A + (size_t)t * 32) + sub);
        float4 b = __ldg((const float4*)(g_B + (size_t)s * 32) + sub);
        *(float4*)(myU + e_sub * 40 + sub * 4) = make_float4(
            fmaxf(a.x + b.x, 0.f), fmaxf(a.y + b.y, 0.f),
            fmaxf(a.z + b.z, 0.f), fmaxf(a.w + b.w, 0.f));
    }
}

// ===================== encoder =====================
__global__ void __launch_bounds__(128, 6) k_enc(const int* __restrict__ ei,
                                                const float* __restrict__ W2,
                                                const float* __restrict__ b2,
                                                const float* __restrict__ mW,
                                                const float* __restrict__ vW, int E) {
    __shared__ __align__(16) float sU[4][32 * 40];
    __shared__ __align__(16) uint4 sB[256];

    fill_B16(W2, sB);
    __syncthreads();

    int lane = threadIdx.x & 31, warp = threadIdx.x >> 5;
    int g_ = lane >> 2, c_ = lane & 3;
    int oct = lane >> 3, sub = lane & 7;
    unsigned bb = (unsigned)__cvta_generic_to_shared(sB) + (unsigned)lane * 16u;

    // P = [mW | vW] (32x4); fragments per kt2 (col g_, rows kt2*16+2c..)
    u32 ph[2][2], pl[2][2];
    #pragma unroll
    for (int kt2 = 0; kt2 < 2; kt2++) {
        int r0 = kt2 * 16 + 2 * c_;
        float p00 = 0.f, p01 = 0.f, p10 = 0.f, p11 = 0.f;
        if (g_ < 2) {
            p00 = mW[r0 * 2 + g_];       p01 = mW[(r0 + 1) * 2 + g_];
            p10 = mW[(r0 + 8) * 2 + g_]; p11 = mW[(r0 + 9) * 2 + g_];
        } else if (g_ < 4) {
            p00 = vW[r0 * 2 + g_ - 2];       p01 = vW[(r0 + 1) * 2 + g_ - 2];
            p10 = vW[(r0 + 8) * 2 + g_ - 2]; p11 = vW[(r0 + 9) * 2 + g_ - 2];
        }
        bsplit(p00, p01, ph[kt2][0], pl[kt2][0]);
        bsplit(p10, p11, ph[kt2][1], pl[kt2][1]);
    }
    float b20[4], b21[4];
    #pragma unroll
    for (int nt = 0; nt < 4; nt++) {
        b20[nt] = b2[nt * 8 + 2 * c_];
        b21[nt] = b2[nt * 8 + 2 * c_ + 1];
    }

    int tb = (blockIdx.x * 4 + warp) * 32;
    if (tb >= E) return;
    int idx = tb + lane;
    int s_all = 0, t_all = 0;
    if (idx < E) { s_all = ei[idx]; t_all = ei[E + idx]; }

    float* myU = &sU[warp][0];
    gather32(s_all, t_all, oct, sub, myU);
    __syncwarp();

    #pragma unroll
    for (int mt = 0; mt < 2; mt++) {
        float d[4][4];
        mma_tile16(myU + mt * 16 * 40, g_, c_, bb, d);

        float d2[4];
        proj_mma(d, b20, b21, ph, pl, d2);

        // reassemble 4 outputs per edge: cols 2,3 live in lane c^1
        float f2 = __shfl_xor_sync(0xffffffffu, d2[0], 1);
        float f3 = __shfl_xor_sync(0xffffffffu, d2[1], 1);
        float f6 = __shfl_xor_sync(0xffffffffu, d2[2], 1);
        float f7 = __shfl_xor_sync(0xffffffffu, d2[3], 1);

        int tga = __shfl_sync(0xffffffffu, t_all, mt * 16 + g_);
        int tgb = __shfl_sync(0xffffffffu, t_all, mt * 16 + 8 + g_);
        if (c_ == 0) {
            int ea = tb + mt * 16 + g_;
            int eb_ = ea + 8;
            if (ea < E) {
                red4(g_sumenc + (size_t)tga * 4, d2[0], d2[1], f2, f3);
                redf(&g_cnt[tga], 1.0f);
            }
            if (eb_ < E) {
                red4(g_sumenc + (size_t)tgb * 4, d2[2], d2[3], f6, f7);
                redf(&g_cnt[tgb], 1.0f);
            }
        }
    }
}

// ---- K4: per-node mid ----
__global__ void k_mid(const float* __restrict__ mb, const float* __restrict__ vb,
                      const float* __restrict__ dW1, const float* __restrict__ db1,
                      const float* __restrict__ eps2,
                      float* __restrict__ out_mu, float* __restrict__ out_lv, int n) {
    __shared__ float sWd[64], sWb[64], sdb1[32], smb[2], svb[2];
    int t = threadIdx.x;
    if (t < 32) {
        sdb1[t] = db1[t];
        sWd[t]      = dW1[t]      - dW1[64 + t];
        sWd[32 + t] = dW1[32 + t] - dW1[96 + t];
        sWb[t]      = dW1[64 + t];
        sWb[32 + t] = dW1[96 + t];
    }
    if (t < 2) { smb[t] = mb[t]; svb[t] = vb[t]; }
    __syncthreads();
    for (int i = blockIdx.x * blockDim.x + t; i < n; i += gridDim.x * blockDim.x) {
        float4 s = ((const float4*)g_sumenc)[i];
        float inv = 1.0f / fmaxf(g_cnt[i], 1.0f);
        float mu0 = s.x * inv + smb[0];
        float mu1 = s.y * inv + smb[1];
        float lv0 = s.z * inv + svb[0];
        float lv1 = s.w * inv + svb[1];
        float2 ep = ((const float2*)eps2)[i];
        float z0 = mu0 + ep.x * expf(0.5f * lv0);
        float z1 = mu1 + ep.y * expf(0.5f * lv1);
        ((float2*)out_mu)[i] = make_float2(mu0, mu1);
        ((float2*)out_lv)[i] = make_float2(lv0, lv1);
        float a[32], b[32];
        #pragma unroll
        for (int o = 0; o < 32; o++) {
            a[o] = sdb1[o] + z0 * sWd[o] + z1 * sWd[32 + o];
            b[o] = z0 * sWb[o] + z1 * sWb[32 + o];
        }
        float4* Ao = (float4*)(g_A + (size_t)i * 32);
        float4* Bo = (float4*)(g_B + (size_t)i * 32);
        #pragma unroll
        for (int q = 0; q < 8; q++) {
            Ao[q] = make_float4(a[4*q], a[4*q+1], a[4*q+2], a[4*q+3]);
            Bo[q] = make_float4(b[4*q], b[4*q+1], b[4*q+2], b[4*q+3]);
        }
    }
}

// ===================== decoder =====================
__global__ void __launch_bounds__(128, 6) k_dec(const int* __restrict__ ei,
                                                const float* __restrict__ W2,
                                                const float* __restrict__ b2,
                                                const float* __restrict__ W3,
                                                const float* __restrict__ b3, int E) {
    __shared__ __align__(16) float sU[4][32 * 40];
    __shared__ __align__(16) uint4 sB[256];

    fill_B16(W2, sB);
    __syncthreads();

    int lane = threadIdx.x & 31, warp = threadIdx.x >> 5;
    int g_ = lane >> 2, c_ = lane & 3;
    int oct = lane >> 3, sub = lane & 7;
    unsigned bb = (unsigned)__cvta_generic_to_shared(sB) + (unsigned)lane * 16u;

    // P = W3 (32x4); fragments per kt2
    u32 ph[2][2], pl[2][2];
    #pragma unroll
    for (int kt2 = 0; kt2 < 2; kt2++) {
        int r0 = kt2 * 16 + 2 * c_;
        float p00 = 0.f, p01 = 0.f, p10 = 0.f, p11 = 0.f;
        if (g_ < 4) {
            p00 = W3[r0 * 4 + g_];       p01 = W3[(r0 + 1) * 4 + g_];
            p10 = W3[(r0 + 8) * 4 + g_]; p11 = W3[(r0 + 9) * 4 + g_];
        }
        bsplit(p00, p01, ph[kt2][0], pl[kt2][0]);
        bsplit(p10, p11, ph[kt2][1], pl[kt2][1]);
    }
    float b20[4], b21[4];
    #pragma unroll
    for (int nt = 0; nt < 4; nt++) {
        b20[nt] = b2[nt * 8 + 2 * c_];
        b21[nt] = b2[nt * 8 + 2 * c_ + 1];
    }
    float b30 = b3[0], b31 = b3[1], b32 = b3[2], b33 = b3[3];

    int tb = (blockIdx.x * 4 + warp) * 32;
    if (tb >= E) return;
    int idx = tb + lane;
    int s_all = 0, t_all = 0;
    if (idx < E) { s_all = ei[idx]; t_all = ei[E + idx]; }

    float* myU = &sU[warp][0];
    gather32(s_all, t_all, oct, sub, myU);
    __syncwarp();

    #pragma unroll
    for (int mt = 0; mt < 2; mt++) {
        float d[4][4];
        mma_tile16(myU + mt * 16 * 40, g_, c_, bb, d);

        float d2[4];
        proj_mma(d, b20, b21, ph, pl, d2);

        float f2 = __shfl_xor_sync(0xffffffffu, d2[0], 1);
        float f3 = __shfl_xor_sync(0xffffffffu, d2[1], 1);
        float f6 = __shfl_xor_sync(0xffffffffu, d2[2], 1);
        float f7 = __shfl_xor_sync(0xffffffffu, d2[3], 1);

        int tga = __shfl_sync(0xffffffffu, t_all, mt * 16 + g_);
        int tgb = __shfl_sync(0xffffffffu, t_all, mt * 16 + 8 + g_);
        if (c_ == 0) {
            int ea = tb + mt * 16 + g_;
            int eb_ = ea + 8;
            if (ea < E)
                red4(g_sumout + (size_t)tga * 4, d2[0] + b30, d2[1] + b31, f2 + b32, f3 + b33);
            if (eb_ < E)
                red4(g_sumout + (size_t)tgb * 4, d2[2] + b30, d2[3] + b31, f6 + b32, f7 + b33);
        }
    }
}

// ---- K6: per-node output mean ----
__global__ void k_out(float* __restrict__ out, int n) {
    for (int i = blockIdx.x * blockDim.x + threadIdx.x; i < n; i += gridDim.x * blockDim.x) {
        float inv = 1.0f / fmaxf(g_cnt[i], 1.0f);
        float4 s = ((const float4*)g_sumout)[i];
        ((float4*)out)[i] = make_float4(s.x * inv, s.y * inv, s.z * inv, s.w * inv);
    }
}

extern "C" void kernel_launch(void* const* d_in, const int* in_sizes, int n_in,
                              void* d_out, int out_size) {
    const float* x     = (const float*)d_in[0];
    const int*   ei    = (const int*)d_in[1];
    const float* eps   = (const float*)d_in[2];
    const float* gamma = (const float*)d_in[3];
    const float* beta  = (const float*)d_in[4];
    const float* eW1   = (const float*)d_in[5];
    const float* eb1   = (const float*)d_in[6];
    const float* eW2   = (const float*)d_in[7];
    const float* eb2   = (const float*)d_in[8];
    const float* mW    = (const float*)d_in[9];
    const float* mb    = (const float*)d_in[10];
    const float* vW    = (const float*)d_in[11];
    const float* vb    = (const float*)d_in[12];
    const float* dW1   = (const float*)d_in[13];
    const float* db1   = (const float*)d_in[14];
    const float* dW2   = (const float*)d_in[15];
    const float* db2   = (const float*)d_in[16];
    const float* dW3   = (const float*)d_in[17];
    const float* db3   = (const float*)d_in[18];

    int n = in_sizes[0] / 4;
    int E = in_sizes[1] / 2;

    float* out    = (float*)d_out;
    float* out_mu = out + (size_t)n * 4;
    float* out_lv = out + (size_t)n * 6;

    int nb = (n + 255) / 256;
    int eb = (E + 127) / 128;

    k_zero<<<256, 256>>>(n);
    k_stats<<<256, 256>>>((const float4*)x, n);
    k_pre<<<nb, 256>>>((const float4*)x, gamma, beta, eW1, eb1, n, 1.0f / (float)n);
    k_enc<<<eb, 128>>>(ei, eW2, eb2, mW, vW, E);
    k_mid<<<nb, 256>>>(mb, vb, dW1, db1, eps, out_mu, out_lv, n);
    k_dec<<<eb, 128>>>(ei, dW2, db2, dW3, db3, E);
    k_out<<<nb, 256>>>(out, n);
}

// round 12
// speedup vs baseline: 2.5764x; 1.0209x over previous
#include <cuda_runtime.h>
#include <math.h>

#define N_MAX 100000
typedef unsigned long long ull;
typedef unsigned int u32;

// ---- scratch ----
__device__ __align__(16) float g_A[N_MAX * 32];
__device__ __align__(16) float g_B[N_MAX * 32];
__device__ __align__(16) float g_sumenc[N_MAX * 4];
__device__ __align__(16) float g_cnt[N_MAX];
__device__ __align__(16) float g_sumout[N_MAX * 4];
__device__ __align__(16) float g_stats[8];

// ---- helpers ----
__device__ __forceinline__ void red4(float* p, float a, float b, float c, float d) {
    asm volatile("red.global.add.v4.f32 [%0], {%1,%2,%3,%4};"
                 :: "l"(p), "f"(a), "f"(b), "f"(c), "f"(d) : "memory");
}
__device__ __forceinline__ void redf(float* p, float v) {
    asm volatile("red.global.add.f32 [%0], %1;" :: "l"(p), "f"(v) : "memory");
}
// pack two f32 -> bf16x2 (lo=x, hi=y)
__device__ __forceinline__ u32 bfpack(float y, float x) {
    u32 r; asm("cvt.rn.bf16x2.f32 %0, %1, %2;" : "=r"(r) : "f"(y), "f"(x)); return r;
}
// split (x,y) into bf16x2 high h and residual l
__device__ __forceinline__ void bsplit(float x, float y, u32& h, u32& l) {
    h = bfpack(y, x);
    float xr = x - __uint_as_float(h << 16);
    float yr = y - __uint_as_float(h & 0xFFFF0000u);
    l = bfpack(yr, xr);
}
__device__ __forceinline__ void mma16(float* d, const u32* a, u32 b0, u32 b1) {
    asm volatile("mma.sync.aligned.m16n8k16.row.col.f32.bf16.bf16.f32 "
                 "{%0,%1,%2,%3},{%4,%5,%6,%7},{%8,%9},{%0,%1,%2,%3};"
                 : "+f"(d[0]), "+f"(d[1]), "+f"(d[2]), "+f"(d[3])
                 : "r"(a[0]), "r"(a[1]), "r"(a[2]), "r"(a[3]), "r"(b0), "r"(b1));
}
__device__ __forceinline__ void lds128(unsigned addr, u32& a, u32& b, u32& c, u32& d) {
    asm volatile("ld.shared.v4.u32 {%0,%1,%2,%3}, [%4];"
                 : "=r"(a), "=r"(b), "=r"(c), "=r"(d) : "r"(addr));
}

// ---- K0: zero stats only (rest folded into k_pre / k_mid) ----
__global__ void k_zero_s() {
    if (threadIdx.x < 8) g_stats[threadIdx.x] = 0.f;
}

// ---- K1: batchnorm statistics ----
__global__ void k_stats(const float4* __restrict__ x, int n) {
    float sx = 0, sy = 0, sz = 0, sw = 0, qx = 0, qy = 0, qz = 0, qw = 0;
    for (int i = blockIdx.x * blockDim.x + threadIdx.x; i < n; i += gridDim.x * blockDim.x) {
        float4 v = x[i];
        sx += v.x; sy += v.y; sz += v.z; sw += v.w;
        qx += v.x * v.x; qy += v.y * v.y; qz += v.z * v.z; qw += v.w * v.w;
    }
    #pragma unroll
    for (int off = 16; off; off >>= 1) {
        sx += __shfl_down_sync(0xffffffffu, sx, off);
        sy += __shfl_down_sync(0xffffffffu, sy, off);
        sz += __shfl_down_sync(0xffffffffu, sz, off);
        sw += __shfl_down_sync(0xffffffffu, sw, off);
        qx += __shfl_down_sync(0xffffffffu, qx, off);
        qy += __shfl_down_sync(0xffffffffu, qy, off);
        qz += __shfl_down_sync(0xffffffffu, qz, off);
        qw += __shfl_down_sync(0xffffffffu, qw, off);
    }
    if ((threadIdx.x & 31) == 0) {
        atomicAdd(&g_stats[0], sx); atomicAdd(&g_stats[1], sy);
        atomicAdd(&g_stats[2], sz); atomicAdd(&g_stats[3], sw);
        atomicAdd(&g_stats[4], qx); atomicAdd(&g_stats[5], qy);
        atomicAdd(&g_stats[6], qz); atomicAdd(&g_stats[7], qw);
    }
}

// ---- K2: BN + encoder layer-1 split (also zeroes sumenc/cnt) ----
__global__ void k_pre(const float4* __restrict__ x,
                      const float* __restrict__ gamma, const float* __restrict__ beta,
                      const float* __restrict__ eW1, const float* __restrict__ eb1,
                      int n, float invN) {
    __shared__ float sWd[128], sWb[128], sb1[32], sScale[4], sShift[4];
    int t = threadIdx.x;
    if (t < 128) {
        int c = t >> 5, o = t & 31;
        float wa = eW1[c * 32 + o], wb = eW1[(4 + c) * 32 + o];
        sWd[t] = wa - wb; sWb[t] = wb;
    }
    if (t < 32) sb1[t] = eb1[t];
    if (t < 4) {
        float m = g_stats[t] * invN;
        float v = g_stats[4 + t] * invN - m * m;
        float s = rsqrtf(v + 1e-5f) * gamma[t];
        sScale[t] = s; sShift[t] = beta[t] - m * s;
    }
    __syncthreads();
    for (int i = blockIdx.x * blockDim.x + t; i < n; i += gridDim.x * blockDim.x) {
        float4 xv = x[i];
        float xn[4];
        xn[0] = xv.x * sScale[0] + sShift[0];
        xn[1] = xv.y * sScale[1] + sShift[1];
        xn[2] = xv.z * sScale[2] + sShift[2];
        xn[3] = xv.w * sScale[3] + sShift[3];
        float a[32], b[32];
        #pragma unroll
        for (int o = 0; o < 32; o++) {
            float av = sb1[o], bv = 0.f;
            #pragma unroll
            for (int c = 0; c < 4; c++) {
                av += xn[c] * sWd[c * 32 + o];
                bv += xn[c] * sWb[c * 32 + o];
            }
            a[o] = av; b[o] = bv;
        }
        float4* Ao = (float4*)(g_A + (size_t)i * 32);
        float4* Bo = (float4*)(g_B + (size_t)i * 32);
        #pragma unroll
        for (int q = 0; q < 8; q++) {
            Ao[q] = make_float4(a[4*q], a[4*q+1], a[4*q+2], a[4*q+3]);
            Bo[q] = make_float4(b[4*q], b[4*q+1], b[4*q+2], b[4*q+3]);
        }
        ((float4*)g_sumenc)[i] = make_float4(0.f, 0.f, 0.f, 0.f);
        g_cnt[i] = 0.f;
    }
}

// ---- fill B tile: slot(kt,nt,lane) = {bh0, bh1, bl0, bl1} ----
__device__ __forceinline__ void fill_B16(const float* __restrict__ W, uint4* sB) {
    for (int idx = threadIdx.x; idx < 256; idx += 128) {
        int kt = idx >> 7, nt = (idx >> 5) & 3, l = idx & 31;
        int g = l >> 2, c = l & 3;
        int col = nt * 8 + g;
        int r0 = kt * 16 + 2 * c;
        float w0 = W[(size_t)r0 * 32 + col];
        float w1 = W[(size_t)(r0 + 1) * 32 + col];
        float w2 = W[(size_t)(r0 + 8) * 32 + col];
        float w3 = W[(size_t)(r0 + 9) * 32 + col];
        u32 h0, l0, h1, l1;
        bsplit(w0, w1, h0, l0);
        bsplit(w2, w3, h1, l1);
        sB[idx] = make_uint4(h0, h1, l0, l1);
    }
}

// ---- dual-tile 3-term bf16 MMA: both 16-row sub-tiles per B load ----
__device__ __forceinline__ void mma_dual(const float* myU, int g_, int c_,
                                         unsigned bb, float d0[4][4], float d1[4][4]) {
    #pragma unroll
    for (int nt = 0; nt < 4; nt++)
        #pragma unroll
        for (int j = 0; j < 4; j++) { d0[nt][j] = 0.f; d1[nt][j] = 0.f; }
    #pragma unroll
    for (int kt = 0; kt < 2; kt++) {
        u32 ah0[4], al0[4], ah1[4], al1[4];
        {
            const float* p0 = myU + g_ * 40 + kt * 16 + 2 * c_;
            const float* p1 = myU + (g_ + 8) * 40 + kt * 16 + 2 * c_;
            float2 f0 = *(const float2*)p0;
            float2 f1 = *(const float2*)p1;
            float2 f2 = *(const float2*)(p0 + 8);
            float2 f3 = *(const float2*)(p1 + 8);
            bsplit(f0.x, f0.y, ah0[0], al0[0]);
            bsplit(f1.x, f1.y, ah0[1], al0[1]);
            bsplit(f2.x, f2.y, ah0[2], al0[2]);
            bsplit(f3.x, f3.y, ah0[3], al0[3]);
        }
        {
            const float* p0 = myU + (16 + g_) * 40 + kt * 16 + 2 * c_;
            const float* p1 = myU + (24 + g_) * 40 + kt * 16 + 2 * c_;
            float2 f0 = *(const float2*)p0;
            float2 f1 = *(const float2*)p1;
            float2 f2 = *(const float2*)(p0 + 8);
            float2 f3 = *(const float2*)(p1 + 8);
            bsplit(f0.x, f0.y, ah1[0], al1[0]);
            bsplit(f1.x, f1.y, ah1[1], al1[1]);
            bsplit(f2.x, f2.y, ah1[2], al1[2]);
            bsplit(f3.x, f3.y, ah1[3], al1[3]);
        }
        #pragma unroll
        for (int nt = 0; nt < 4; nt++) {
            u32 b0, b1, c0, c1;
            lds128(bb + (unsigned)(kt * 4 + nt) * 512u, b0, b1, c0, c1);
            mma16(d0[nt], ah0, b0, b1);
            mma16(d0[nt], al0, b0, b1);
            mma16(d0[nt], ah0, c0, c1);
            mma16(d1[nt], ah1, b0, b1);
            mma16(d1[nt], al1, b0, b1);
            mma16(d1[nt], ah1, c0, c1);
        }
    }
}

// ---- projection MMA: msg(32cols as k) @ P(32x4); d frags -> d2 frags ----
__device__ __forceinline__ void proj_mma(const float d[4][4],
                                         const float b20[4], const float b21[4],
                                         const u32 ph[2][2], const u32 pl[2][2],
                                         float d2[4]) {
    d2[0] = d2[1] = d2[2] = d2[3] = 0.f;
    #pragma unroll
    for (int kt2 = 0; kt2 < 2; kt2++) {
        int n0 = 2 * kt2, n1 = n0 + 1;
        float m00 = fmaxf(d[n0][0] + b20[n0], 0.f);
        float m01 = fmaxf(d[n0][1] + b21[n0], 0.f);
        float m02 = fmaxf(d[n0][2] + b20[n0], 0.f);
        float m03 = fmaxf(d[n0][3] + b21[n0], 0.f);
        float m10 = fmaxf(d[n1][0] + b20[n1], 0.f);
        float m11 = fmaxf(d[n1][1] + b21[n1], 0.f);
        float m12 = fmaxf(d[n1][2] + b20[n1], 0.f);
        float m13 = fmaxf(d[n1][3] + b21[n1], 0.f);
        u32 ah[4], al[4];
        bsplit(m00, m01, ah[0], al[0]);
        bsplit(m02, m03, ah[1], al[1]);
        bsplit(m10, m11, ah[2], al[2]);
        bsplit(m12, m13, ah[3], al[3]);
        mma16(d2, ah, ph[kt2][0], ph[kt2][1]);
        mma16(d2, al, ph[kt2][0], ph[kt2][1]);
        mma16(d2, ah, pl[kt2][0], pl[kt2][1]);
    }
}

// ---- octet gather: 8 lanes per edge, one full 128B row per LDG line ----
__device__ __forceinline__ void gather32(int s_all, int t_all, int oct, int sub, float* myU) {
    #pragma unroll
    for (int p = 0; p < 8; p++) {
        int e_sub = 4 * p + oct;
        int s = __shfl_sync(0xffffffffu, s_all, e_sub);
        int t = __shfl_sync(0xffffffffu, t_all, e_sub);
        float4 a = __ldg((const float4*)(g_A + (size_t)t * 32) + sub);
        float4 b = __ldg((const float4*)(g_B + (size_t)s * 32) + sub);
        *(float4*)(myU + e_sub * 40 + sub * 4) = make_float4(
            fmaxf(a.x + b.x, 0.f), fmaxf(a.y + b.y, 0.f),
            fmaxf(a.z + b.z, 0.f), fmaxf(a.w + b.w, 0.f));
    }
}

// ===================== encoder =====================
__global__ void __launch_bounds__(128, 5) k_enc(const int* __restrict__ ei,
                                                const float* __restrict__ W2,
                                                const float* __restrict__ b2,
                                                const float* __restrict__ mW,
                                                const float* __restrict__ vW, int E) {
    __shared__ __align__(16) float sU[4][32 * 40];
    __shared__ __align__(16) uint4 sB[256];

    fill_B16(W2, sB);
    __syncthreads();

    int lane = threadIdx.x & 31, warp = threadIdx.x >> 5;
    int g_ = lane >> 2, c_ = lane & 3;
    int oct = lane >> 3, sub = lane & 7;
    unsigned bb = (unsigned)__cvta_generic_to_shared(sB) + (unsigned)lane * 16u;

    // P = [mW | vW] (32x4); fragments per kt2
    u32 ph[2][2], pl[2][2];
    #pragma unroll
    for (int kt2 = 0; kt2 < 2; kt2++) {
        int r0 = kt2 * 16 + 2 * c_;
        float p00 = 0.f, p01 = 0.f, p10 = 0.f, p11 = 0.f;
        if (g_ < 2) {
            p00 = mW[r0 * 2 + g_];       p01 = mW[(r0 + 1) * 2 + g_];
            p10 = mW[(r0 + 8) * 2 + g_]; p11 = mW[(r0 + 9) * 2 + g_];
        } else if (g_ < 4) {
            p00 = vW[r0 * 2 + g_ - 2];       p01 = vW[(r0 + 1) * 2 + g_ - 2];
            p10 = vW[(r0 + 8) * 2 + g_ - 2]; p11 = vW[(r0 + 9) * 2 + g_ - 2];
        }
        bsplit(p00, p01, ph[kt2][0], pl[kt2][0]);
        bsplit(p10, p11, ph[kt2][1], pl[kt2][1]);
    }
    float b20[4], b21[4];
    #pragma unroll
    for (int nt = 0; nt < 4; nt++) {
        b20[nt] = b2[nt * 8 + 2 * c_];
        b21[nt] = b2[nt * 8 + 2 * c_ + 1];
    }

    int tb = (blockIdx.x * 4 + warp) * 32;
    if (tb >= E) return;
    int idx = tb + lane;
    int s_all = 0, t_all = 0;
    if (idx < E) { s_all = ei[idx]; t_all = ei[E + idx]; }

    float* myU = &sU[warp][0];
    gather32(s_all, t_all, oct, sub, myU);
    __syncwarp();

    float dd[2][4][4];
    mma_dual(myU, g_, c_, bb, dd[0], dd[1]);

    #pragma unroll
    for (int mt = 0; mt < 2; mt++) {
        float d2[4];
        proj_mma(dd[mt], b20, b21, ph, pl, d2);

        float f2 = __shfl_xor_sync(0xffffffffu, d2[0], 1);
        float f3 = __shfl_xor_sync(0xffffffffu, d2[1], 1);
        float f6 = __shfl_xor_sync(0xffffffffu, d2[2], 1);
        float f7 = __shfl_xor_sync(0xffffffffu, d2[3], 1);

        int tga = __shfl_sync(0xffffffffu, t_all, mt * 16 + g_);
        int tgb = __shfl_sync(0xffffffffu, t_all, mt * 16 + 8 + g_);
        if (c_ == 0) {
            int ea = tb + mt * 16 + g_;
            int eb_ = ea + 8;
            if (ea < E) {
                red4(g_sumenc + (size_t)tga * 4, d2[0], d2[1], f2, f3);
                redf(&g_cnt[tga], 1.0f);
            }
            if (eb_ < E) {
                red4(g_sumenc + (size_t)tgb * 4, d2[2], d2[3], f6, f7);
                redf(&g_cnt[tgb], 1.0f);
            }
        }
    }
}

// ---- K4: per-node mid (also zeroes sumout) ----
__global__ void k_mid(const float* __restrict__ mb, const float* __restrict__ vb,
                      const float* __restrict__ dW1, const float* __restrict__ db1,
                      const float* __restrict__ eps2,
                      float* __restrict__ out_mu, float* __restrict__ out_lv, int n) {
    __shared__ float sWd[64], sWb[64], sdb1[32], smb[2], svb[2];
    int t = threadIdx.x;
    if (t < 32) {
        sdb1[t] = db1[t];
        sWd[t]      = dW1[t]      - dW1[64 + t];
        sWd[32 + t] = dW1[32 + t] - dW1[96 + t];
        sWb[t]      = dW1[64 + t];
        sWb[32 + t] = dW1[96 + t];
    }
    if (t < 2) { smb[t] = mb[t]; svb[t] = vb[t]; }
    __syncthreads();
    for (int i = blockIdx.x * blockDim.x + t; i < n; i += gridDim.x * blockDim.x) {
        float4 s = ((const float4*)g_sumenc)[i];
        float inv = 1.0f / fmaxf(g_cnt[i], 1.0f);
        float mu0 = s.x * inv + smb[0];
        float mu1 = s.y * inv + smb[1];
        float lv0 = s.z * inv + svb[0];
        float lv1 = s.w * inv + svb[1];
        float2 ep = ((const float2*)eps2)[i];
        float z0 = mu0 + ep.x * expf(0.5f * lv0);
        float z1 = mu1 + ep.y * expf(0.5f * lv1);
        ((float2*)out_mu)[i] = make_float2(mu0, mu1);
        ((float2*)out_lv)[i] = make_float2(lv0, lv1);
        float a[32], b[32];
        #pragma unroll
        for (int o = 0; o < 32; o++) {
            a[o] = sdb1[o] + z0 * sWd[o] + z1 * sWd[32 + o];
            b[o] = z0 * sWb[o] + z1 * sWb[32 + o];
        }
        float4* Ao = (float4*)(g_A + (size_t)i * 32);
        float4* Bo = (float4*)(g_B + (size_t)i * 32);
        #pragma unroll
        for (int q = 0; q < 8; q++) {
            Ao[q] = make_float4(a[4*q], a[4*q+1], a[4*q+2], a[4*q+3]);
            Bo[q] = make_float4(b[4*q], b[4*q+1], b[4*q+2], b[4*q+3]);
        }
        ((float4*)g_sumout)[i] = make_float4(0.f, 0.f, 0.f, 0.f);
    }
}

// ===================== decoder =====================
__global__ void __launch_bounds__(128, 5) k_dec(const int* __restrict__ ei,
                                                const float* __restrict__ W2,
                                                const float* __restrict__ b2,
                                                const float* __restrict__ W3,
                                                const float* __restrict__ b3, int E) {
    __shared__ __align__(16) float sU[4][32 * 40];
    __shared__ __align__(16) uint4 sB[256];

    fill_B16(W2, sB);
    __syncthreads();

    int lane = threadIdx.x & 31, warp = threadIdx.x >> 5;
    int g_ = lane >> 2, c_ = lane & 3;
    int oct = lane >> 3, sub = lane & 7;
    unsigned bb = (unsigned)__cvta_generic_to_shared(sB) + (unsigned)lane * 16u;

    // P = W3 (32x4)
    u32 ph[2][2], pl[2][2];
    #pragma unroll
    for (int kt2 = 0; kt2 < 2; kt2++) {
        int r0 = kt2 * 16 + 2 * c_;
        float p00 = 0.f, p01 = 0.f, p10 = 0.f, p11 = 0.f;
        if (g_ < 4) {
            p00 = W3[r0 * 4 + g_];       p01 = W3[(r0 + 1) * 4 + g_];
            p10 = W3[(r0 + 8) * 4 + g_]; p11 = W3[(r0 + 9) * 4 + g_];
        }
        bsplit(p00, p01, ph[kt2][0], pl[kt2][0]);
        bsplit(p10, p11, ph[kt2][1], pl[kt2][1]);
    }
    float b20[4], b21[4];
    #pragma unroll
    for (int nt = 0; nt < 4; nt++) {
        b20[nt] = b2[nt * 8 + 2 * c_];
        b21[nt] = b2[nt * 8 + 2 * c_ + 1];
    }
    float b30 = b3[0], b31 = b3[1], b32 = b3[2], b33 = b3[3];

    int tb = (blockIdx.x * 4 + warp) * 32;
    if (tb >= E) return;
    int idx = tb + lane;
    int s_all = 0, t_all = 0;
    if (idx < E) { s_all = ei[idx]; t_all = ei[E + idx]; }

    float* myU = &sU[warp][0];
    gather32(s_all, t_all, oct, sub, myU);
    __syncwarp();

    float dd[2][4][4];
    mma_dual(myU, g_, c_, bb, dd[0], dd[1]);

    #pragma unroll
    for (int mt = 0; mt < 2; mt++) {
        float d2[4];
        proj_mma(dd[mt], b20, b21, ph, pl, d2);

        float f2 = __shfl_xor_sync(0xffffffffu, d2[0], 1);
        float f3 = __shfl_xor_sync(0xffffffffu, d2[1], 1);
        float f6 = __shfl_xor_sync(0xffffffffu, d2[2], 1);
        float f7 = __shfl_xor_sync(0xffffffffu, d2[3], 1);

        int tga = __shfl_sync(0xffffffffu, t_all, mt * 16 + g_);
        int tgb = __shfl_sync(0xffffffffu, t_all, mt * 16 + 8 + g_);
        if (c_ == 0) {
            int ea = tb + mt * 16 + g_;
            int eb_ = ea + 8;
            if (ea < E)
                red4(g_sumout + (size_t)tga * 4, d2[0] + b30, d2[1] + b31, f2 + b32, f3 + b33);
            if (eb_ < E)
                red4(g_sumout + (size_t)tgb * 4, d2[2] + b30, d2[3] + b31, f6 + b32, f7 + b33);
        }
    }
}

// ---- K6: per-node output mean ----
__global__ void k_out(float* __restrict__ out, int n) {
    for (int i = blockIdx.x * blockDim.x + threadIdx.x; i < n; i += gridDim.x * blockDim.x) {
        float inv = 1.0f / fmaxf(g_cnt[i], 1.0f);
        float4 s = ((const float4*)g_sumout)[i];
        ((float4*)out)[i] = make_float4(s.x * inv, s.y * inv, s.z * inv, s.w * inv);
    }
}

extern "C" void kernel_launch(void* const* d_in, const int* in_sizes, int n_in,
                              void* d_out, int out_size) {
    const float* x     = (const float*)d_in[0];
    const int*   ei    = (const int*)d_in[1];
    const float* eps   = (const float*)d_in[2];
    const float* gamma = (const float*)d_in[3];
    const float* beta  = (const float*)d_in[4];
    const float* eW1   = (const float*)d_in[5];
    const float* eb1   = (const float*)d_in[6];
    const float* eW2   = (const float*)d_in[7];
    const float* eb2   = (const float*)d_in[8];
    const float* mW    = (const float*)d_in[9];
    const float* mb    = (const float*)d_in[10];
    const float* vW    = (const float*)d_in[11];
    const float* vb    = (const float*)d_in[12];
    const float* dW1   = (const float*)d_in[13];
    const float* db1   = (const float*)d_in[14];
    const float* dW2   = (const float*)d_in[15];
    const float* db2   = (const float*)d_in[16];
    const float* dW3   = (const float*)d_in[17];
    const float* db3   = (const float*)d_in[18];

    int n = in_sizes[0] / 4;
    int E = in_sizes[1] / 2;

    float* out    = (float*)d_out;
    float* out_mu = out + (size_t)n * 4;
    float* out_lv = out + (size_t)n * 6;

    int nb = (n + 255) / 256;
    int eb = (E + 127) / 128;

    k_zero_s<<<1, 32>>>();
    k_stats<<<256, 256>>>((const float4*)x, n);
    k_pre<<<nb, 256>>>((const float4*)x, gamma, beta, eW1, eb1, n, 1.0f / (float)n);
    k_enc<<<eb, 128>>>(ei, eW2, eb2, mW, vW, E);
    k_mid<<<nb, 256>>>(mb, vb, dW1, db1, eps, out_mu, out_lv, n);
    k_dec<<<eb, 128>>>(ei, dW2, db2, dW3, db3, E);
    k_out<<<nb, 256>>>(out, n);
}

// round 13
// speedup vs baseline: 2.9020x; 1.1264x over previous
#include <cuda_runtime.h>
#include <math.h>

#define N_MAX 100000
typedef unsigned long long ull;
typedef unsigned int u32;

// ---- scratch ----
__device__ __align__(16) float g_A[N_MAX * 32];
__device__ __align__(16) float g_B[N_MAX * 32];
__device__ __align__(16) float g_sumenc[N_MAX * 4];
__device__ __align__(16) float g_cnt[N_MAX];
__device__ __align__(16) float g_sumout[N_MAX * 4];
__device__ __align__(16) float g_stats[8];

// ---- helpers ----
__device__ __forceinline__ void red4(float* p, float a, float b, float c, float d) {
    asm volatile("red.global.add.v4.f32 [%0], {%1,%2,%3,%4};"
                 :: "l"(p), "f"(a), "f"(b), "f"(c), "f"(d) : "memory");
}
__device__ __forceinline__ void redf(float* p, float v) {
    asm volatile("red.global.add.f32 [%0], %1;" :: "l"(p), "f"(v) : "memory");
}
__device__ __forceinline__ u32 bfpack(float y, float x) {
    u32 r; asm("cvt.rn.bf16x2.f32 %0, %1, %2;" : "=r"(r) : "f"(y), "f"(x)); return r;
}
__device__ __forceinline__ void bsplit(float x, float y, u32& h, u32& l) {
    h = bfpack(y, x);
    float xr = x - __uint_as_float(h << 16);
    float yr = y - __uint_as_float(h & 0xFFFF0000u);
    l = bfpack(yr, xr);
}
__device__ __forceinline__ void mma16(float* d, const u32* a, u32 b0, u32 b1) {
    asm volatile("mma.sync.aligned.m16n8k16.row.col.f32.bf16.bf16.f32 "
                 "{%0,%1,%2,%3},{%4,%5,%6,%7},{%8,%9},{%0,%1,%2,%3};"
                 : "+f"(d[0]), "+f"(d[1]), "+f"(d[2]), "+f"(d[3])
                 : "r"(a[0]), "r"(a[1]), "r"(a[2]), "r"(a[3]), "r"(b0), "r"(b1));
}
__device__ __forceinline__ void lds128(unsigned addr, u32& a, u32& b, u32& c, u32& d) {
    asm volatile("ld.shared.v4.u32 {%0,%1,%2,%3}, [%4];"
                 : "=r"(a), "=r"(b), "=r"(c), "=r"(d) : "r"(addr));
}
__device__ __forceinline__ void ldmx4(u32* r, unsigned addr) {
    asm volatile("ldmatrix.sync.aligned.m8n8.x4.shared.b16 {%0,%1,%2,%3}, [%4];"
                 : "=r"(r[0]), "=r"(r[1]), "=r"(r[2]), "=r"(r[3]) : "r"(addr));
}

// ---- K0: zero stats only ----
__global__ void k_zero_s() {
    if (threadIdx.x < 8) g_stats[threadIdx.x] = 0.f;
}

// ---- K1: batchnorm statistics ----
__global__ void k_stats(const float4* __restrict__ x, int n) {
    float sx = 0, sy = 0, sz = 0, sw = 0, qx = 0, qy = 0, qz = 0, qw = 0;
    for (int i = blockIdx.x * blockDim.x + threadIdx.x; i < n; i += gridDim.x * blockDim.x) {
        float4 v = x[i];
        sx += v.x; sy += v.y; sz += v.z; sw += v.w;
        qx += v.x * v.x; qy += v.y * v.y; qz += v.z * v.z; qw += v.w * v.w;
    }
    #pragma unroll
    for (int off = 16; off; off >>= 1) {
        sx += __shfl_down_sync(0xffffffffu, sx, off);
        sy += __shfl_down_sync(0xffffffffu, sy, off);
        sz += __shfl_down_sync(0xffffffffu, sz, off);
        sw += __shfl_down_sync(0xffffffffu, sw, off);
        qx += __shfl_down_sync(0xffffffffu, qx, off);
        qy += __shfl_down_sync(0xffffffffu, qy, off);
        qz += __shfl_down_sync(0xffffffffu, qz, off);
        qw += __shfl_down_sync(0xffffffffu, qw, off);
    }
    if ((threadIdx.x & 31) == 0) {
        atomicAdd(&g_stats[0], sx); atomicAdd(&g_stats[1], sy);
        atomicAdd(&g_stats[2], sz); atomicAdd(&g_stats[3], sw);
        atomicAdd(&g_stats[4], qx); atomicAdd(&g_stats[5], qy);
        atomicAdd(&g_stats[6], qz); atomicAdd(&g_stats[7], qw);
    }
}

// ---- K2: BN + encoder layer-1 split (also zeroes sumenc/cnt) ----
__global__ void k_pre(const float4* __restrict__ x,
                      const float* __restrict__ gamma, const float* __restrict__ beta,
                      const float* __restrict__ eW1, const float* __restrict__ eb1,
                      int n, float invN) {
    __shared__ float sWd[128], sWb[128], sb1[32], sScale[4], sShift[4];
    int t = threadIdx.x;
    if (t < 128) {
        int c = t >> 5, o = t & 31;
        float wa = eW1[c * 32 + o], wb = eW1[(4 + c) * 32 + o];
        sWd[t] = wa - wb; sWb[t] = wb;
    }
    if (t < 32) sb1[t] = eb1[t];
    if (t < 4) {
        float m = g_stats[t] * invN;
        float v = g_stats[4 + t] * invN - m * m;
        float s = rsqrtf(v + 1e-5f) * gamma[t];
        sScale[t] = s; sShift[t] = beta[t] - m * s;
    }
    __syncthreads();
    for (int i = blockIdx.x * blockDim.x + t; i < n; i += gridDim.x * blockDim.x) {
        float4 xv = x[i];
        float xn[4];
        xn[0] = xv.x * sScale[0] + sShift[0];
        xn[1] = xv.y * sScale[1] + sShift[1];
        xn[2] = xv.z * sScale[2] + sShift[2];
        xn[3] = xv.w * sScale[3] + sShift[3];
        float a[32], b[32];
        #pragma unroll
        for (int o = 0; o < 32; o++) {
            float av = sb1[o], bv = 0.f;
            #pragma unroll
            for (int c = 0; c < 4; c++) {
                av += xn[c] * sWd[c * 32 + o];
                bv += xn[c] * sWb[c * 32 + o];
            }
            a[o] = av; b[o] = bv;
        }
        float4* Ao = (float4*)(g_A + (size_t)i * 32);
        float4* Bo = (float4*)(g_B + (size_t)i * 32);
        #pragma unroll
        for (int q = 0; q < 8; q++) {
            Ao[q] = make_float4(a[4*q], a[4*q+1], a[4*q+2], a[4*q+3]);
            Bo[q] = make_float4(b[4*q], b[4*q+1], b[4*q+2], b[4*q+3]);
        }
        ((float4*)g_sumenc)[i] = make_float4(0.f, 0.f, 0.f, 0.f);
        g_cnt[i] = 0.f;
    }
}

// ---- fill B staging tile: slot(kt,nt,lane) = {bh0, bh1, bl0, bl1} ----
__device__ __forceinline__ void fill_B16(const float* __restrict__ W, uint4* sB) {
    for (int idx = threadIdx.x; idx < 256; idx += 128) {
        int kt = idx >> 7, nt = (idx >> 5) & 3, l = idx & 31;
        int g = l >> 2, c = l & 3;
        int col = nt * 8 + g;
        int r0 = kt * 16 + 2 * c;
        float w0 = W[(size_t)r0 * 32 + col];
        float w1 = W[(size_t)(r0 + 1) * 32 + col];
        float w2 = W[(size_t)(r0 + 8) * 32 + col];
        float w3 = W[(size_t)(r0 + 9) * 32 + col];
        u32 h0, l0, h1, l1;
        bsplit(w0, w1, h0, l0);
        bsplit(w2, w3, h1, l1);
        sB[idx] = make_uint4(h0, h1, l0, l1);
    }
}

// ---- octet gather with bf16 split into uh/ul tiles (row stride 20 u32 = 80B) ----
__device__ __forceinline__ void gather32b(int s_all, int t_all, int oct, int sub,
                                          u32* sUh, u32* sUl) {
    #pragma unroll
    for (int p = 0; p < 8; p++) {
        int e_sub = 4 * p + oct;
        int s = __shfl_sync(0xffffffffu, s_all, e_sub);
        int t = __shfl_sync(0xffffffffu, t_all, e_sub);
        float4 a = __ldg((const float4*)(g_A + (size_t)t * 32) + sub);
        float4 b = __ldg((const float4*)(g_B + (size_t)s * 32) + sub);
        float u0 = fmaxf(a.x + b.x, 0.f);
        float u1 = fmaxf(a.y + b.y, 0.f);
        float u2 = fmaxf(a.z + b.z, 0.f);
        float u3 = fmaxf(a.w + b.w, 0.f);
        u32 h01, l01, h23, l23;
        bsplit(u0, u1, h01, l01);
        bsplit(u2, u3, h23, l23);
        *(uint2*)(sUh + e_sub * 20 + sub * 2) = make_uint2(h01, h23);
        *(uint2*)(sUl + e_sub * 20 + sub * 2) = make_uint2(l01, l23);
    }
}

// ---- projection MMA (unchanged math) ----
__device__ __forceinline__ void proj_mma(const float d[4][4],
                                         const float b20[4], const float b21[4],
                                         const u32 ph[2][2], const u32 pl[2][2],
                                         float d2[4]) {
    d2[0] = d2[1] = d2[2] = d2[3] = 0.f;
    #pragma unroll
    for (int kt2 = 0; kt2 < 2; kt2++) {
        int n0 = 2 * kt2, n1 = n0 + 1;
        float m00 = fmaxf(d[n0][0] + b20[n0], 0.f);
        float m01 = fmaxf(d[n0][1] + b21[n0], 0.f);
        float m02 = fmaxf(d[n0][2] + b20[n0], 0.f);
        float m03 = fmaxf(d[n0][3] + b21[n0], 0.f);
        float m10 = fmaxf(d[n1][0] + b20[n1], 0.f);
        float m11 = fmaxf(d[n1][1] + b21[n1], 0.f);
        float m12 = fmaxf(d[n1][2] + b20[n1], 0.f);
        float m13 = fmaxf(d[n1][3] + b21[n1], 0.f);
        u32 ah[4], al[4];
        bsplit(m00, m01, ah[0], al[0]);
        bsplit(m02, m03, ah[1], al[1]);
        bsplit(m10, m11, ah[2], al[2]);
        bsplit(m12, m13, ah[3], al[3]);
        mma16(d2, ah, ph[kt2][0], ph[kt2][1]);
        mma16(d2, al, ph[kt2][0], ph[kt2][1]);
        mma16(d2, ah, pl[kt2][0], pl[kt2][1]);
    }
}

#define TPW 4   // tiles (of 32 edges) per warp

// ===================== encoder =====================
__global__ void __launch_bounds__(128, 5) k_enc(const int* __restrict__ ei,
                                                const float* __restrict__ W2,
                                                const float* __restrict__ b2,
                                                const float* __restrict__ mW,
                                                const float* __restrict__ vW, int E) {
    __shared__ __align__(16) u32 sUh[4][32 * 20];
    __shared__ __align__(16) u32 sUl[4][32 * 20];
    __shared__ __align__(16) uint4 sB[256];

    fill_B16(W2, sB);
    __syncthreads();

    int lane = threadIdx.x & 31, warp = threadIdx.x >> 5;
    int g_ = lane >> 2, c_ = lane & 3;
    int oct = lane >> 3, sub = lane & 7;

    // B fragments into registers (once per warp)
    u32 Bh[2][4][2], Bl[2][4][2];
    {
        unsigned bb = (unsigned)__cvta_generic_to_shared(sB) + (unsigned)lane * 16u;
        #pragma unroll
        for (int kt = 0; kt < 2; kt++)
            #pragma unroll
            for (int nt = 0; nt < 4; nt++)
                lds128(bb + (unsigned)(kt * 4 + nt) * 512u,
                       Bh[kt][nt][0], Bh[kt][nt][1], Bl[kt][nt][0], Bl[kt][nt][1]);
    }

    // P = [mW | vW]
    u32 ph[2][2], pl[2][2];
    #pragma unroll
    for (int kt2 = 0; kt2 < 2; kt2++) {
        int r0 = kt2 * 16 + 2 * c_;
        float p00 = 0.f, p01 = 0.f, p10 = 0.f, p11 = 0.f;
        if (g_ < 2) {
            p00 = mW[r0 * 2 + g_];       p01 = mW[(r0 + 1) * 2 + g_];
            p10 = mW[(r0 + 8) * 2 + g_]; p11 = mW[(r0 + 9) * 2 + g_];
        } else if (g_ < 4) {
            p00 = vW[r0 * 2 + g_ - 2];       p01 = vW[(r0 + 1) * 2 + g_ - 2];
            p10 = vW[(r0 + 8) * 2 + g_ - 2]; p11 = vW[(r0 + 9) * 2 + g_ - 2];
        }
        bsplit(p00, p01, ph[kt2][0], pl[kt2][0]);
        bsplit(p10, p11, ph[kt2][1], pl[kt2][1]);
    }
    float b20[4], b21[4];
    #pragma unroll
    for (int nt = 0; nt < 4; nt++) {
        b20[nt] = b2[nt * 8 + 2 * c_];
        b21[nt] = b2[nt * 8 + 2 * c_ + 1];
    }

    u32* myUh = &sUh[warp][0];
    u32* myUl = &sUl[warp][0];
    unsigned uhb = (unsigned)__cvta_generic_to_shared(myUh)
                 + (unsigned)((lane & 15) * 80 + (lane >> 4) * 16);
    unsigned ulb = (unsigned)__cvta_generic_to_shared(myUl)
                 + (unsigned)((lane & 15) * 80 + (lane >> 4) * 16);

    int tile0 = (blockIdx.x * 4 + warp) * TPW;
    #pragma unroll 1
    for (int it = 0; it < TPW; it++) {
        int tb = (tile0 + it) * 32;
        if (tb >= E) break;
        int idx = tb + lane;
        int s_all = 0, t_all = 0;
        if (idx < E) { s_all = ei[idx]; t_all = ei[E + idx]; }

        gather32b(s_all, t_all, oct, sub, myUh, myUl);
        __syncwarp();

        #pragma unroll
        for (int mt = 0; mt < 2; mt++) {
            float d[4][4];
            #pragma unroll
            for (int nt = 0; nt < 4; nt++)
                #pragma unroll
                for (int j = 0; j < 4; j++) d[nt][j] = 0.f;
            #pragma unroll
            for (int kt = 0; kt < 2; kt++) {
                u32 ah[4], al[4];
                unsigned off = (unsigned)(mt * 16 * 80 + kt * 32);
                ldmx4(ah, uhb + off);
                ldmx4(al, ulb + off);
                #pragma unroll
                for (int nt = 0; nt < 4; nt++) {
                    mma16(d[nt], ah, Bh[kt][nt][0], Bh[kt][nt][1]);
                    mma16(d[nt], al, Bh[kt][nt][0], Bh[kt][nt][1]);
                    mma16(d[nt], ah, Bl[kt][nt][0], Bl[kt][nt][1]);
                }
            }

            float d2[4];
            proj_mma(d, b20, b21, ph, pl, d2);

            float f2 = __shfl_xor_sync(0xffffffffu, d2[0], 1);
            float f3 = __shfl_xor_sync(0xffffffffu, d2[1], 1);
            float f6 = __shfl_xor_sync(0xffffffffu, d2[2], 1);
            float f7 = __shfl_xor_sync(0xffffffffu, d2[3], 1);

            int tga = __shfl_sync(0xffffffffu, t_all, mt * 16 + g_);
            int tgb = __shfl_sync(0xffffffffu, t_all, mt * 16 + 8 + g_);
            if (c_ == 0) {
                int ea = tb + mt * 16 + g_;
                int eb_ = ea + 8;
                if (ea < E) {
                    red4(g_sumenc + (size_t)tga * 4, d2[0], d2[1], f2, f3);
                    redf(&g_cnt[tga], 1.0f);
                }
                if (eb_ < E) {
                    red4(g_sumenc + (size_t)tgb * 4, d2[2], d2[3], f6, f7);
                    redf(&g_cnt[tgb], 1.0f);
                }
            }
        }
        __syncwarp();
    }
}

// ---- K4: per-node mid (also zeroes sumout) ----
__global__ void k_mid(const float* __restrict__ mb, const float* __restrict__ vb,
                      const float* __restrict__ dW1, const float* __restrict__ db1,
                      const float* __restrict__ eps2,
                      float* __restrict__ out_mu, float* __restrict__ out_lv, int n) {
    __shared__ float sWd[64], sWb[64], sdb1[32], smb[2], svb[2];
    int t = threadIdx.x;
    if (t < 32) {
        sdb1[t] = db1[t];
        sWd[t]      = dW1[t]      - dW1[64 + t];
        sWd[32 + t] = dW1[32 + t] - dW1[96 + t];
        sWb[t]      = dW1[64 + t];
        sWb[32 + t] = dW1[96 + t];
    }
    if (t < 2) { smb[t] = mb[t]; svb[t] = vb[t]; }
    __syncthreads();
    for (int i = blockIdx.x * blockDim.x + t; i < n; i += gridDim.x * blockDim.x) {
        float4 s = ((const float4*)g_sumenc)[i];
        float inv = 1.0f / fmaxf(g_cnt[i], 1.0f);
        float mu0 = s.x * inv + smb[0];
        float mu1 = s.y * inv + smb[1];
        float lv0 = s.z * inv + svb[0];
        float lv1 = s.w * inv + svb[1];
        float2 ep = ((const float2*)eps2)[i];
        float z0 = mu0 + ep.x * expf(0.5f * lv0);
        float z1 = mu1 + ep.y * expf(0.5f * lv1);
        ((float2*)out_mu)[i] = make_float2(mu0, mu1);
        ((float2*)out_lv)[i] = make_float2(lv0, lv1);
        float a[32], b[32];
        #pragma unroll
        for (int o = 0; o < 32; o++) {
            a[o] = sdb1[o] + z0 * sWd[o] + z1 * sWd[32 + o];
            b[o] = z0 * sWb[o] + z1 * sWb[32 + o];
        }
        float4* Ao = (float4*)(g_A + (size_t)i * 32);
        float4* Bo = (float4*)(g_B + (size_t)i * 32);
        #pragma unroll
        for (int q = 0; q < 8; q++) {
            Ao[q] = make_float4(a[4*q], a[4*q+1], a[4*q+2], a[4*q+3]);
            Bo[q] = make_float4(b[4*q], b[4*q+1], b[4*q+2], b[4*q+3]);
        }
        ((float4*)g_sumout)[i] = make_float4(0.f, 0.f, 0.f, 0.f);
    }
}

// ===================== decoder =====================
__global__ void __launch_bounds__(128, 5) k_dec(const int* __restrict__ ei,
                                                const float* __restrict__ W2,
                                                const float* __restrict__ b2,
                                                const float* __restrict__ W3,
                                                const float* __restrict__ b3, int E) {
    __shared__ __align__(16) u32 sUh[4][32 * 20];
    __shared__ __align__(16) u32 sUl[4][32 * 20];
    __shared__ __align__(16) uint4 sB[256];

    fill_B16(W2, sB);
    __syncthreads();

    int lane = threadIdx.x & 31, warp = threadIdx.x >> 5;
    int g_ = lane >> 2, c_ = lane & 3;
    int oct = lane >> 3, sub = lane & 7;

    u32 Bh[2][4][2], Bl[2][4][2];
    {
        unsigned bb = (unsigned)__cvta_generic_to_shared(sB) + (unsigned)lane * 16u;
        #pragma unroll
        for (int kt = 0; kt < 2; kt++)
            #pragma unroll
            for (int nt = 0; nt < 4; nt++)
                lds128(bb + (unsigned)(kt * 4 + nt) * 512u,
                       Bh[kt][nt][0], Bh[kt][nt][1], Bl[kt][nt][0], Bl[kt][nt][1]);
    }

    // P = W3
    u32 ph[2][2], pl[2][2];
    #pragma unroll
    for (int kt2 = 0; kt2 < 2; kt2++) {
        int r0 = kt2 * 16 + 2 * c_;
        float p00 = 0.f, p01 = 0.f, p10 = 0.f, p11 = 0.f;
        if (g_ < 4) {
            p00 = W3[r0 * 4 + g_];       p01 = W3[(r0 + 1) * 4 + g_];
            p10 = W3[(r0 + 8) * 4 + g_]; p11 = W3[(r0 + 9) * 4 + g_];
        }
        bsplit(p00, p01, ph[kt2][0], pl[kt2][0]);
        bsplit(p10, p11, ph[kt2][1], pl[kt2][1]);
    }
    float b20[4], b21[4];
    #pragma unroll
    for (int nt = 0; nt < 4; nt++) {
        b20[nt] = b2[nt * 8 + 2 * c_];
        b21[nt] = b2[nt * 8 + 2 * c_ + 1];
    }
    float b30 = b3[0], b31 = b3[1], b32 = b3[2], b33 = b3[3];

    u32* myUh = &sUh[warp][0];
    u32* myUl = &sUl[warp][0];
    unsigned uhb = (unsigned)__cvta_generic_to_shared(myUh)
                 + (unsigned)((lane & 15) * 80 + (lane >> 4) * 16);
    unsigned ulb = (unsigned)__cvta_generic_to_shared(myUl)
                 + (unsigned)((lane & 15) * 80 + (lane >> 4) * 16);

    int tile0 = (blockIdx.x * 4 + warp) * TPW;
    #pragma unroll 1
    for (int it = 0; it < TPW; it++) {
        int tb = (tile0 + it) * 32;
        if (tb >= E) break;
        int idx = tb + lane;
        int s_all = 0, t_all = 0;
        if (idx < E) { s_all = ei[idx]; t_all = ei[E + idx]; }

        gather32b(s_all, t_all, oct, sub, myUh, myUl);
        __syncwarp();

        #pragma unroll
        for (int mt = 0; mt < 2; mt++) {
            float d[4][4];
            #pragma unroll
            for (int nt = 0; nt < 4; nt++)
                #pragma unroll
                for (int j = 0; j < 4; j++) d[nt][j] = 0.f;
            #pragma unroll
            for (int kt = 0; kt < 2; kt++) {
                u32 ah[4], al[4];
                unsigned off = (unsigned)(mt * 16 * 80 + kt * 32);
                ldmx4(ah, uhb + off);
                ldmx4(al, ulb + off);
                #pragma unroll
                for (int nt = 0; nt < 4; nt++) {
                    mma16(d[nt], ah, Bh[kt][nt][0], Bh[kt][nt][1]);
                    mma16(d[nt], al, Bh[kt][nt][0], Bh[kt][nt][1]);
                    mma16(d[nt], ah, Bl[kt][nt][0], Bl[kt][nt][1]);
                }
            }

            float d2[4];
            proj_mma(d, b20, b21, ph, pl, d2);

            float f2 = __shfl_xor_sync(0xffffffffu, d2[0], 1);
            float f3 = __shfl_xor_sync(0xffffffffu, d2[1], 1);
            float f6 = __shfl_xor_sync(0xffffffffu, d2[2], 1);
            float f7 = __shfl_xor_sync(0xffffffffu, d2[3], 1);

            int tga = __shfl_sync(0xffffffffu, t_all, mt * 16 + g_);
            int tgb = __shfl_sync(0xffffffffu, t_all, mt * 16 + 8 + g_);
            if (c_ == 0) {
                int ea = tb + mt * 16 + g_;
                int eb_ = ea + 8;
                if (ea < E)
                    red4(g_sumout + (size_t)tga * 4, d2[0] + b30, d2[1] + b31, f2 + b32, f3 + b33);
                if (eb_ < E)
                    red4(g_sumout + (size_t)tgb * 4, d2[2] + b30, d2[3] + b31, f6 + b32, f7 + b33);
            }
        }
        __syncwarp();
    }
}

// ---- K6: per-node output mean ----
__global__ void k_out(float* __restrict__ out, int n) {
    for (int i = blockIdx.x * blockDim.x + threadIdx.x; i < n; i += gridDim.x * blockDim.x) {
        float inv = 1.0f / fmaxf(g_cnt[i], 1.0f);
        float4 s = ((const float4*)g_sumout)[i];
        ((float4*)out)[i] = make_float4(s.x * inv, s.y * inv, s.z * inv, s.w * inv);
    }
}

extern "C" void kernel_launch(void* const* d_in, const int* in_sizes, int n_in,
                              void* d_out, int out_size) {
    const float* x     = (const float*)d_in[0];
    const int*   ei    = (const int*)d_in[1];
    const float* eps   = (const float*)d_in[2];
    const float* gamma = (const float*)d_in[3];
    const float* beta  = (const float*)d_in[4];
    const float* eW1   = (const float*)d_in[5];
    const float* eb1   = (const float*)d_in[6];
    const float* eW2   = (const float*)d_in[7];
    const float* eb2   = (const float*)d_in[8];
    const float* mW    = (const float*)d_in[9];
    const float* mb    = (const float*)d_in[10];
    const float* vW    = (const float*)d_in[11];
    const float* vb    = (const float*)d_in[12];
    const float* dW1   = (const float*)d_in[13];
    const float* db1   = (const float*)d_in[14];
    const float* dW2   = (const float*)d_in[15];
    const float* db2   = (const float*)d_in[16];
    const float* dW3   = (const float*)d_in[17];
    const float* db3   = (const float*)d_in[18];

    int n = in_sizes[0] / 4;
    int E = in_sizes[1] / 2;

    float* out    = (float*)d_out;
    float* out_mu = out + (size_t)n * 4;
    float* out_lv = out + (size_t)n * 6;

    int nb = (n + 255) / 256;
    int eb = (E + 128 * TPW - 1) / (128 * TPW);   // 512 edges per block

    k_zero_s<<<1, 32>>>();
    k_stats<<<256, 256>>>((const float4*)x, n);
    k_pre<<<nb, 256>>>((const float4*)x, gamma, beta, eW1, eb1, n, 1.0f / (float)n);
    k_enc<<<eb, 128>>>(ei, eW2, eb2, mW, vW, E);
    k_mid<<<nb, 256>>>(mb, vb, dW1, db1, eps, out_mu, out_lv, n);
    k_dec<<<eb, 128>>>(ei, dW2, db2, dW3, db3, E);
    k_out<<<nb, 256>>>(out, n);
}